// round 14
// baseline (speedup 1.0000x reference)
#include <cuda_runtime.h>
#include <cuda_bf16.h>
#include <math.h>
#include <stdint.h>

// Problem dims
#define NB    32
#define LENZ  512
#define LCPD  128
#define DENZ  1280
#define DCPD  256
#define DOUT  512

static constexpr float INV_SCALE = 0.04419417382415922f; // 1/sqrt(512)

// ==================== scratch (fp32) ====================
static constexpr size_t SZ_S_BIG = (size_t)NB * LENZ * LCPD;
static constexpr size_t SZ_BCE   = 1536;
static constexpr size_t SZ_BCS   = 1024;
static constexpr size_t SZ_BCP   = 1024;
static constexpr size_t SZ_WB1   = (size_t)NB * LCPD;
static constexpr size_t SZ_WB2   = (size_t)NB * LENZ;
static constexpr size_t SZ_WB3   = (size_t)NB * LCPD;
static constexpr size_t SZ_WB4   = (size_t)NB * LENZ;
static constexpr size_t SZ_XB1   = (size_t)NB * DCPD;
static constexpr size_t SZ_XB3   = (size_t)NB * DCPD;
static constexpr size_t SZ_XB2   = (size_t)NB * DENZ;
static constexpr size_t SZ_XB4   = (size_t)NB * DENZ;

static constexpr size_t OFF_S1    = 0;
static constexpr size_t OFF_S2    = OFF_S1 + SZ_S_BIG;
static constexpr size_t OFF_S3    = OFF_S2 + SZ_S_BIG;
static constexpr size_t OFF_S4    = OFF_S3 + SZ_S_BIG;
static constexpr size_t OFF_BCE   = OFF_S4 + SZ_S_BIG;
static constexpr size_t OFF_BCS   = OFF_BCE + SZ_BCE;
static constexpr size_t OFF_BCP   = OFF_BCS + SZ_BCS;
static constexpr size_t OFF_WB1   = OFF_BCP + SZ_BCP;
static constexpr size_t OFF_WB2   = OFF_WB1 + SZ_WB1;
static constexpr size_t OFF_WB3   = OFF_WB2 + SZ_WB2;
static constexpr size_t OFF_WB4   = OFF_WB3 + SZ_WB3;
static constexpr size_t OFF_XB1   = OFF_WB4 + SZ_WB4;
static constexpr size_t OFF_XB3   = OFF_XB1 + SZ_XB1;
static constexpr size_t OFF_XB2   = OFF_XB3 + SZ_XB3;
static constexpr size_t OFF_XB4   = OFF_XB2 + SZ_XB2;
static constexpr size_t SCRATCH_TOTAL = OFF_XB4 + SZ_XB4;
static constexpr size_t ZERO_LEN = SZ_WB1 + SZ_WB2 + SZ_WB3 + SZ_WB4 + SZ_XB1 + SZ_XB3; // 57344
static_assert(OFF_XB1 == OFF_WB1 + SZ_WB1 + SZ_WB2 + SZ_WB3 + SZ_WB4, "zero region contiguity");
static_assert(OFF_XB3 == OFF_XB1 + SZ_XB1, "zero region contiguity");

static __device__ float g_scratch[SCRATCH_TOTAL];

// bf16 hi/lo operands
static __device__ __align__(16) __nv_bfloat16 g_Ah[(size_t)NB * LENZ * DENZ];
static __device__ __align__(16) __nv_bfloat16 g_Al[(size_t)NB * LENZ * DENZ];
static __device__ __align__(16) __nv_bfloat16 g_Wht[(size_t)1536 * DENZ];   // [1536,1280]
static __device__ __align__(16) __nv_bfloat16 g_Wlt[(size_t)1536 * DENZ];
static __device__ __align__(16) __nv_bfloat16 g_X2h[(size_t)2 * NB * LCPD * DCPD]; // subs|prod
static __device__ __align__(16) __nv_bfloat16 g_X2l[(size_t)2 * NB * LCPD * DCPD];
static __device__ __align__(16) __nv_bfloat16 g_W2h[(size_t)2 * 1024 * DCPD];      // [1024,256] x2
static __device__ __align__(16) __nv_bfloat16 g_W2l[(size_t)2 * 1024 * DCPD];
// projection outputs as bf16 hi/lo
static __device__ __align__(16) __nv_bfloat16 g_QKh[(size_t)NB * LENZ * 1536];
static __device__ __align__(16) __nv_bfloat16 g_QKl[(size_t)NB * LENZ * 1536];
static __device__ __align__(16) __nv_bfloat16 g_Ch[(size_t)2 * NB * LCPD * 1024];  // sub|prod
static __device__ __align__(16) __nv_bfloat16 g_Cl[(size_t)2 * NB * LCPD * 1024];

static constexpr size_t CPOFF = (size_t)NB * LCPD * 1024;  // prod offset in g_Ch/g_Cl

// ==================== merged head kernel ====================
static constexpr size_t N_ENZ  = (size_t)NB * LENZ * DENZ;
static constexpr size_t N_W    = (size_t)1536 * DENZ;
static constexpr size_t N_CPD  = (size_t)NB * LCPD * DCPD;
static constexpr size_t N_W2   = (size_t)1024 * DCPD;

static constexpr int HB0 = (int)(N_ENZ / 1024);
static constexpr int HB1 = HB0 + (int)(N_W / 1024);
static constexpr int HB2 = HB1 + (int)(N_CPD / 1024);
static constexpr int HB3 = HB2 + (int)(N_CPD / 1024);
static constexpr int HB4 = HB3 + (int)(N_W2 / 1024);
static constexpr int HB5 = HB4 + (int)(N_W2 / 1024);
static constexpr int HB6 = HB5 + 6;
static constexpr int HB7 = HB6 + 4;
static constexpr int HB8 = HB7 + 4;
static constexpr int HB9 = HB8 + (int)(ZERO_LEN / 1024);
static_assert((size_t)HB0 * 1024 == N_ENZ, "convA range");
static_assert((size_t)(HB1 - HB0) * 1024 == N_W, "convW range");
static_assert((size_t)(HB3 - HB2) * 1024 == N_CPD, "convX range");
static_assert((size_t)(HB5 - HB4) * 1024 == N_W2, "convW2 range");
static_assert((size_t)(HB9 - HB8) * 1024 == ZERO_LEN, "zero range");

__device__ __forceinline__ void split4_store(const float* xs, __nv_bfloat16* H,
                                             __nv_bfloat16* L, size_t i) {
    unsigned short hs[4], ls[4];
#pragma unroll
    for (int j = 0; j < 4; j++) {
        __nv_bfloat16 h = __float2bfloat16(xs[j]);
        hs[j] = __bfloat16_as_ushort(h);
        ls[j] = __bfloat16_as_ushort(__float2bfloat16(xs[j] - __bfloat162float(h)));
    }
    *(uint2*)(H + i) = make_uint2((uint32_t)hs[0] | ((uint32_t)hs[1] << 16),
                                  (uint32_t)hs[2] | ((uint32_t)hs[3] << 16));
    *(uint2*)(L + i) = make_uint2((uint32_t)ls[0] | ((uint32_t)ls[1] << 16),
                                  (uint32_t)ls[2] | ((uint32_t)ls[3] << 16));
}

__global__ void head_kernel(const float* __restrict__ enz,
                            const float* __restrict__ subs,
                            const float* __restrict__ prod,
                            const float* __restrict__ enz_Wq, const float* __restrict__ enz_bq,
                            const float* __restrict__ enz_Wk, const float* __restrict__ enz_bk,
                            const float* __restrict__ sub_Wq, const float* __restrict__ sub_bq,
                            const float* __restrict__ sub_Wk, const float* __restrict__ sub_bk,
                            const float* __restrict__ prod_Wq, const float* __restrict__ prod_bq,
                            const float* __restrict__ prod_Wk, const float* __restrict__ prod_bk) {
    const int blk = blockIdx.x;
    const int tid = threadIdx.x;

    if (blk < HB0) {
        size_t i = ((size_t)blk * 256 + tid) * 4;
        float4 v = *(const float4*)(enz + i);
        float xs[4] = {v.x, v.y, v.z, v.w};
        split4_store(xs, g_Ah, g_Al, i);
    } else if (blk < HB1) {
        size_t flat = ((size_t)(blk - HB0) * 256 + tid) * 4;
        int n = (int)(flat / DENZ), k = (int)(flat % DENZ);
        const float* src; int nn = n;
        if (n < 512)       src = enz_Wq;
        else if (n < 1024) { src = sub_Wk;  nn = n - 512; }
        else               { src = prod_Wk; nn = n - 1024; }
        float xs[4];
#pragma unroll
        for (int j = 0; j < 4; j++) xs[j] = src[(size_t)(k + j) * 512 + nn];
        split4_store(xs, g_Wht, g_Wlt, flat);
    } else if (blk < HB2) {
        size_t i = ((size_t)(blk - HB1) * 256 + tid) * 4;
        float4 v = *(const float4*)(subs + i);
        float xs[4] = {v.x, v.y, v.z, v.w};
        split4_store(xs, g_X2h, g_X2l, i);
    } else if (blk < HB3) {
        size_t i = ((size_t)(blk - HB2) * 256 + tid) * 4;
        float4 v = *(const float4*)(prod + i);
        float xs[4] = {v.x, v.y, v.z, v.w};
        split4_store(xs, g_X2h + N_CPD, g_X2l + N_CPD, i);
    } else if (blk < HB4) {
        size_t flat = ((size_t)(blk - HB3) * 256 + tid) * 4;
        int n = (int)(flat / DCPD), k = (int)(flat % DCPD);
        const float* src = (n < 512) ? enz_Wk : sub_Wq;
        int nn = (n < 512) ? n : n - 512;
        float xs[4];
#pragma unroll
        for (int j = 0; j < 4; j++) xs[j] = src[(size_t)(k + j) * 512 + nn];
        split4_store(xs, g_W2h, g_W2l, flat);
    } else if (blk < HB5) {
        size_t flat = ((size_t)(blk - HB4) * 256 + tid) * 4;
        int n = (int)(flat / DCPD), k = (int)(flat % DCPD);
        const float* src = (n < 512) ? enz_Wk : prod_Wq;
        int nn = (n < 512) ? n : n - 512;
        float xs[4];
#pragma unroll
        for (int j = 0; j < 4; j++) xs[j] = src[(size_t)(k + j) * 512 + nn];
        split4_store(xs, g_W2h + N_W2, g_W2l + N_W2, flat);
    } else if (blk < HB6) {
        int c = (blk - HB5) * 256 + tid;
        if (c < 1536) {
            float v;
            if (c < 512)       v = enz_bq[c];
            else if (c < 1024) v = sub_bk[c - 512];
            else               v = prod_bk[c - 1024];
            g_scratch[OFF_BCE + c] = v;
        }
    } else if (blk < HB7) {
        int c = (blk - HB6) * 256 + tid;
        if (c < 1024)
            g_scratch[OFF_BCS + c] = (c < 512) ? enz_bk[c] : sub_bq[c - 512];
    } else if (blk < HB8) {
        int c = (blk - HB7) * 256 + tid;
        if (c < 1024)
            g_scratch[OFF_BCP + c] = (c < 512) ? enz_bk[c] : prod_bq[c - 512];
    } else if (blk < HB9) {
        size_t i = ((size_t)(blk - HB8) * 256 + tid) * 4;
        if (i < ZERO_LEN)
            *(float4*)&g_scratch[OFF_WB1 + i] = make_float4(0.f, 0.f, 0.f, 0.f);
    }
}

// ==================== HMMA helpers ====================
#define MMA_BF16(d, a, b) \
    asm volatile("mma.sync.aligned.m16n8k16.row.col.f32.bf16.bf16.f32 " \
                 "{%0,%1,%2,%3}, {%4,%5,%6,%7}, {%8,%9}, {%0,%1,%2,%3};" \
                 : "+f"((d)[0]), "+f"((d)[1]), "+f"((d)[2]), "+f"((d)[3]) \
                 : "r"((a)[0]), "r"((a)[1]), "r"((a)[2]), "r"((a)[3]), \
                   "r"((b)[0]), "r"((b)[1]))

#define LDSM_X4(r0, r1, r2, r3, addr) \
    asm volatile("ldmatrix.sync.aligned.m8n8.x4.shared.b16 {%0,%1,%2,%3}, [%4];" \
                 : "=r"(r0), "=r"(r1), "=r"(r2), "=r"(r3) : "r"(addr))

// cp.async: L2 -> smem, 16B, bypasses L1 and register file (sm_80+ baseline PTX)
#define CP_ASYNC16(smem_u32, gptr) \
    asm volatile("cp.async.cg.shared.global [%0], [%1], 16;" \
                 :: "r"(smem_u32), "l"(gptr) : "memory")
#define CP_COMMIT() asm volatile("cp.async.commit_group;" ::: "memory")
#define CP_WAIT0()  asm volatile("cp.async.wait_group 0;" ::: "memory")
#define CP_WAIT1()  asm volatile("cp.async.wait_group 1;" ::: "memory")

__device__ __forceinline__ uint32_t smem_u32_of(const void* p) {
    uint32_t a;
    asm("{ .reg .u64 t; cvta.to.shared.u64 t, %1; cvt.u32.u64 %0, t; }" : "=r"(a) : "l"(p));
    return a;
}

__device__ __forceinline__ uint32_t pack_hi2(float v0, float v1, uint32_t& lo_out) {
    __nv_bfloat16 h0 = __float2bfloat16(v0);
    __nv_bfloat16 h1 = __float2bfloat16(v1);
    __nv_bfloat16 l0 = __float2bfloat16(v0 - __bfloat162float(h0));
    __nv_bfloat16 l1 = __float2bfloat16(v1 - __bfloat162float(h1));
    lo_out = (uint32_t)__bfloat16_as_ushort(l0) | ((uint32_t)__bfloat16_as_ushort(l1) << 16);
    return (uint32_t)__bfloat16_as_ushort(h0) | ((uint32_t)__bfloat16_as_ushort(h1) << 16);
}

static constexpr int KCH = 32;
static constexpr int ROW_W = 20;                // 16 data words + 4 pad (80B: 16B-aligned rows)
static constexpr int TILE_W = 128 * ROW_W;      // 2560 words
static constexpr int STAGE_W = 4 * TILE_W;
static constexpr int SMEM_MMA_BYTES = 2 * STAGE_W * 4;  // 81920
static_assert((ROW_W * 4) % 16 == 0, "row stride must be 16B-aligned for cp.async");

// Fill one stage: each thread issues 8 cp.async of 16B (2 per operand array).
// u in 0..511: r = u>>2 (row), c16 = u&3 (16B group within 64B row).
__device__ __forceinline__ void fill_stage(uint32_t st_base, int tid,
                                           const __nv_bfloat16* Ah, const __nv_bfloat16* Al,
                                           const __nv_bfloat16* Bh, const __nv_bfloat16* Bl,
                                           int bm, int bn, int lda, int ldb, int k0) {
#pragma unroll
    for (int i = 0; i < 2; i++) {
        int u = tid + i * 256;
        int r = u >> 2, c16 = u & 3;
        uint32_t so = st_base + (uint32_t)(r * ROW_W + c16 * 4) * 4;
        size_t ga = (size_t)(bm + r) * lda + k0 + c16 * 8;
        size_t gb = (size_t)(bn + r) * ldb + k0 + c16 * 8;
        CP_ASYNC16(so + 0 * TILE_W * 4, Ah + ga);
        CP_ASYNC16(so + 1 * TILE_W * 4, Al + ga);
        CP_ASYNC16(so + 2 * TILE_W * 4, Bh + gb);
        CP_ASYNC16(so + 3 * TILE_W * 4, Bl + gb);
    }
}

// ==================== generic HMMA NN projection (bf16 hi/lo out) ====================
__global__ __launch_bounds__(256, 1)
void hmma_nn_kernel(const __nv_bfloat16* __restrict__ Ah, const __nv_bfloat16* __restrict__ Al,
                    const __nv_bfloat16* __restrict__ Bh, const __nv_bfloat16* __restrict__ Bl,
                    const float* __restrict__ bias,
                    __nv_bfloat16* __restrict__ Ch, __nv_bfloat16* __restrict__ Cl,
                    int K, int ldc) {
    extern __shared__ uint32_t smw[];
    const int tid  = threadIdx.x;
    const int lane = tid & 31;
    const int w    = tid >> 5;
    const int wm   = w & 1;
    const int wn   = w >> 1;
    const int r4   = lane >> 2;
    const int tg   = lane & 3;
    const int bm   = blockIdx.y * 128;
    const int bn   = blockIdx.x * 128;
    const int NCHUNK = K / KCH;
    const uint32_t smem0 = smem_u32_of(smw);

    const int lrow = lane & 7, grp = lane >> 3;
    const int a_row_off = ((grp & 1) << 3) + lrow;
    const int a_kh = (grp >> 1) * 4;
    const int b_row_off = ((grp >> 1) << 3) + lrow;
    const int b_kh = (grp & 1) * 4;

    float acc[4][4][4];
#pragma unroll
    for (int i = 0; i < 4; i++)
#pragma unroll
        for (int j = 0; j < 4; j++)
#pragma unroll
            for (int q = 0; q < 4; q++) acc[i][j][q] = 0.f;

    fill_stage(smem0, tid, Ah, Al, Bh, Bl, bm, bn, K, K, 0);
    CP_COMMIT();

    for (int ch = 0; ch < NCHUNK; ch++) {
        const int cur = ch & 1;
        if (ch + 1 < NCHUNK) {
            fill_stage(smem0 + ((cur ^ 1) * STAGE_W) * 4, tid, Ah, Al, Bh, Bl,
                       bm, bn, K, K, (ch + 1) * KCH);
            CP_COMMIT();
            CP_WAIT1();
        } else {
            CP_WAIT0();
        }
        __syncthreads();

        const uint32_t stAh = smem0 + (cur * STAGE_W) * 4;
        const uint32_t stAl = stAh + TILE_W * 4;
        const uint32_t stBh = stAh + 2 * TILE_W * 4;
        const uint32_t stBl = stAh + 3 * TILE_W * 4;

#pragma unroll
        for (int ks = 0; ks < 2; ks++) {
            const int kw = ks * 8;
            uint32_t ah[4][4], al[4][4], bh[4][2], bl[4][2];
#pragma unroll
            for (int mi = 0; mi < 4; mi++) {
                uint32_t wo = (uint32_t)((wm * 64 + mi * 16 + a_row_off) * ROW_W + kw + a_kh) * 4;
                LDSM_X4(ah[mi][0], ah[mi][1], ah[mi][2], ah[mi][3], stAh + wo);
                LDSM_X4(al[mi][0], al[mi][1], al[mi][2], al[mi][3], stAl + wo);
            }
#pragma unroll
            for (int p = 0; p < 2; p++) {
                uint32_t wo = (uint32_t)((wn * 32 + p * 16 + b_row_off) * ROW_W + kw + b_kh) * 4;
                uint32_t t0, t1, t2, t3;
                LDSM_X4(t0, t1, t2, t3, stBh + wo);
                bh[2 * p][0] = t0; bh[2 * p][1] = t1;
                bh[2 * p + 1][0] = t2; bh[2 * p + 1][1] = t3;
                LDSM_X4(t0, t1, t2, t3, stBl + wo);
                bl[2 * p][0] = t0; bl[2 * p][1] = t1;
                bl[2 * p + 1][0] = t2; bl[2 * p + 1][1] = t3;
            }
#pragma unroll
            for (int mi = 0; mi < 4; mi++)
#pragma unroll
                for (int ni = 0; ni < 4; ni++) {
                    MMA_BF16(acc[mi][ni], ah[mi], bh[ni]);
                    MMA_BF16(acc[mi][ni], ah[mi], bl[ni]);
                    MMA_BF16(acc[mi][ni], al[mi], bh[ni]);
                }
        }
        __syncthreads();   // protect buffer before it is refilled two iterations later
    }

#pragma unroll
    for (int ni = 0; ni < 4; ni++) {
        int col = bn + wn * 32 + ni * 8 + tg * 2;
        float b0 = bias[col], b1 = bias[col + 1];
#pragma unroll
        for (int mi = 0; mi < 4; mi++) {
            int row0 = bm + wm * 64 + mi * 16 + r4;
            float v00 = acc[mi][ni][0] + b0, v01 = acc[mi][ni][1] + b1;
            float v10 = acc[mi][ni][2] + b0, v11 = acc[mi][ni][3] + b1;
            uint32_t lo0, lo1;
            uint32_t hi0 = pack_hi2(v00, v01, lo0);
            uint32_t hi1 = pack_hi2(v10, v11, lo1);
            size_t o0 = (size_t)row0 * ldc + col;
            size_t o1 = (size_t)(row0 + 8) * ldc + col;
            *(uint32_t*)(Ch + o0) = hi0;
            *(uint32_t*)(Cl + o0) = lo0;
            *(uint32_t*)(Ch + o1) = hi1;
            *(uint32_t*)(Cl + o1) = lo1;
        }
    }
}

// ==================== merged score GEMM (all 4 mats, one launch) ====================
__global__ __launch_bounds__(256, 1)
void score_kernel(const float* __restrict__ IW) {
    extern __shared__ uint32_t smw[];
    const int tid  = threadIdx.x;
    const int lane = tid & 31;
    const int w    = tid >> 5;
    const int wm   = w & 1;
    const int wn   = w >> 1;
    const int r4   = lane >> 2;
    const int tg   = lane & 3;
    const int z    = blockIdx.z;
    const int job  = z >> 5;
    const int b    = z & 31;
    const int tile = blockIdx.x;
    const int NCHUNK = DOUT / KCH;   // 16
    const uint32_t smem0 = smem_u32_of(smw);

    const int lrow = lane & 7, grp = lane >> 3;
    const int a_row_off = ((grp & 1) << 3) + lrow;
    const int a_kh = (grp >> 1) * 4;
    const int b_row_off = ((grp >> 1) << 3) + lrow;
    const int b_kh = (grp & 1) * 4;

    const size_t sQK = (size_t)LENZ * 1536;
    const size_t sCP = (size_t)LCPD * 1024;
    const size_t sIW = (size_t)LCPD * LENZ;

    const __nv_bfloat16 *Ah, *Al, *Bh, *Bl;
    int lda, ldb, M, N, biasMode;
    float* S;
    if (job == 0) {
        Ah = g_QKh; Al = g_QKl; lda = 1536;
        Bh = g_Ch;  Bl = g_Cl;  ldb = 1024;
        M = LENZ; N = LCPD; biasMode = 1; S = g_scratch + OFF_S1;
        Ah += (size_t)b * sQK; Al += (size_t)b * sQK;
        Bh += (size_t)b * sCP; Bl += (size_t)b * sCP;
    } else if (job == 1) {
        Ah = g_Ch + 512; Al = g_Cl + 512; lda = 1024;
        Bh = g_QKh + 512; Bl = g_QKl + 512; ldb = 1536;
        M = LCPD; N = LENZ; biasMode = 2; S = g_scratch + OFF_S2;
        Ah += (size_t)b * sCP; Al += (size_t)b * sCP;
        Bh += (size_t)b * sQK; Bl += (size_t)b * sQK;
    } else if (job == 2) {
        Ah = g_QKh; Al = g_QKl; lda = 1536;
        Bh = g_Ch + CPOFF; Bl = g_Cl + CPOFF; ldb = 1024;
        M = LENZ; N = LCPD; biasMode = 0; S = g_scratch + OFF_S3;
        Ah += (size_t)b * sQK; Al += (size_t)b * sQK;
        Bh += (size_t)b * sCP; Bl += (size_t)b * sCP;
    } else {
        Ah = g_Ch + CPOFF + 512; Al = g_Cl + CPOFF + 512; lda = 1024;
        Bh = g_QKh + 1024; Bl = g_QKl + 1024; ldb = 1536;
        M = LCPD; N = LENZ; biasMode = 0; S = g_scratch + OFF_S4;
        Ah += (size_t)b * sCP; Al += (size_t)b * sCP;
        Bh += (size_t)b * sQK; Bl += (size_t)b * sQK;
    }
    S += (size_t)b * (size_t)M * N;
    const float* bias = IW + (size_t)b * sIW;

    const int bm = (M == LENZ) ? tile * 128 : 0;
    const int bn = (M == LENZ) ? 0 : tile * 128;

    float acc[4][4][4];
#pragma unroll
    for (int i = 0; i < 4; i++)
#pragma unroll
        for (int j = 0; j < 4; j++)
#pragma unroll
            for (int q = 0; q < 4; q++) acc[i][j][q] = 0.f;

    fill_stage(smem0, tid, Ah, Al, Bh, Bl, bm, bn, lda, ldb, 0);
    CP_COMMIT();

    for (int ch = 0; ch < NCHUNK; ch++) {
        const int cur = ch & 1;
        if (ch + 1 < NCHUNK) {
            fill_stage(smem0 + ((cur ^ 1) * STAGE_W) * 4, tid, Ah, Al, Bh, Bl,
                       bm, bn, lda, ldb, (ch + 1) * KCH);
            CP_COMMIT();
            CP_WAIT1();
        } else {
            CP_WAIT0();
        }
        __syncthreads();

        const uint32_t stAh = smem0 + (cur * STAGE_W) * 4;
        const uint32_t stAl = stAh + TILE_W * 4;
        const uint32_t stBh = stAh + 2 * TILE_W * 4;
        const uint32_t stBl = stAh + 3 * TILE_W * 4;

#pragma unroll
        for (int ks = 0; ks < 2; ks++) {
            const int kw = ks * 8;
            uint32_t ah[4][4], al[4][4], bh[4][2], bl[4][2];
#pragma unroll
            for (int mi = 0; mi < 4; mi++) {
                uint32_t wo = (uint32_t)((wm * 64 + mi * 16 + a_row_off) * ROW_W + kw + a_kh) * 4;
                LDSM_X4(ah[mi][0], ah[mi][1], ah[mi][2], ah[mi][3], stAh + wo);
                LDSM_X4(al[mi][0], al[mi][1], al[mi][2], al[mi][3], stAl + wo);
            }
#pragma unroll
            for (int p = 0; p < 2; p++) {
                uint32_t wo = (uint32_t)((wn * 32 + p * 16 + b_row_off) * ROW_W + kw + b_kh) * 4;
                uint32_t t0, t1, t2, t3;
                LDSM_X4(t0, t1, t2, t3, stBh + wo);
                bh[2 * p][0] = t0; bh[2 * p][1] = t1;
                bh[2 * p + 1][0] = t2; bh[2 * p + 1][1] = t3;
                LDSM_X4(t0, t1, t2, t3, stBl + wo);
                bl[2 * p][0] = t0; bl[2 * p][1] = t1;
                bl[2 * p + 1][0] = t2; bl[2 * p + 1][1] = t3;
            }
#pragma unroll
            for (int mi = 0; mi < 4; mi++)
#pragma unroll
                for (int ni = 0; ni < 4; ni++) {
                    MMA_BF16(acc[mi][ni], ah[mi], bh[ni]);
                    MMA_BF16(acc[mi][ni], ah[mi], bl[ni]);
                    MMA_BF16(acc[mi][ni], al[mi], bh[ni]);
                }
        }
        __syncthreads();
    }

#pragma unroll
    for (int ni = 0; ni < 4; ni++) {
        int n0 = bn + wn * 32 + ni * 8 + tg * 2;
#pragma unroll
        for (int mi = 0; mi < 4; mi++) {
            int m0 = bm + wm * 64 + mi * 16 + r4;
#pragma unroll
            for (int half = 0; half < 2; half++) {
                int m = m0 + half * 8;
                float v0 = acc[mi][ni][half * 2 + 0] * INV_SCALE;
                float v1 = acc[mi][ni][half * 2 + 1] * INV_SCALE;
                if (biasMode == 1) {
                    v0 += bias[(size_t)n0 * M + m];
                    v1 += bias[(size_t)(n0 + 1) * M + m];
                } else if (biasMode == 2) {
                    v0 += bias[(size_t)m * N + n0];
                    v1 += bias[(size_t)m * N + n0 + 1];
                }
                *(float2*)&S[(size_t)m * N + n0] = make_float2(v0, v1);
            }
        }
    }
}

// ==================== merged softmax + mean -> wbar ====================
template <int LK>
__device__ __forceinline__ void softmax_body(const float* __restrict__ S, float* __restrict__ wbar,
                                             int Lq, int rowsPerBlock, int r0, float* colsum) {
    constexpr int EPL = LK / 32;
    int w = threadIdx.x / 32, lane = threadIdx.x % 32;
    int nw = blockDim.x / 32;

    for (int i = threadIdx.x; i < LK; i += blockDim.x) colsum[i] = 0.f;
    __syncthreads();

    for (int r = r0 + w; r < r0 + rowsPerBlock; r += nw) {
        const float* row = S + (size_t)r * LK;
        float v[EPL];
        float mx = -1e30f;
#pragma unroll
        for (int c = 0; c < EPL / 4; c++) {
            float4 t = *(const float4*)(row + c * 128 + lane * 4);
            v[c * 4 + 0] = t.x; v[c * 4 + 1] = t.y; v[c * 4 + 2] = t.z; v[c * 4 + 3] = t.w;
            mx = fmaxf(mx, fmaxf(fmaxf(t.x, t.y), fmaxf(t.z, t.w)));
        }
#pragma unroll
        for (int o = 16; o > 0; o >>= 1) mx = fmaxf(mx, __shfl_xor_sync(0xffffffffu, mx, o));
        float s = 0.f;
#pragma unroll
        for (int i = 0; i < EPL; i++) { v[i] = __expf(v[i] - mx); s += v[i]; }
#pragma unroll
        for (int o = 16; o > 0; o >>= 1) s += __shfl_xor_sync(0xffffffffu, s, o);
        float inv = 1.f / s;
#pragma unroll
        for (int c = 0; c < EPL / 4; c++)
#pragma unroll
            for (int j = 0; j < 4; j++)
                atomicAdd(&colsum[c * 128 + lane * 4 + j], v[c * 4 + j] * inv);
    }
    __syncthreads();
    float invLq = 1.f / (float)Lq;
    for (int i = threadIdx.x; i < LK; i += blockDim.x)
        atomicAdd(&wbar[i], colsum[i] * invLq);
}

__global__ void softmax_all(void) {
    __shared__ float colsum[512];
    int job = blockIdx.z;
    int b = blockIdx.x;
    int yc = blockIdx.y;
    float* gs = g_scratch;
    if (job == 0) {
        softmax_body<128>(gs + OFF_S1 + (size_t)b * LENZ * LCPD,
                          gs + OFF_WB1 + (size_t)b * LCPD, LENZ, 64, yc * 64, colsum);
    } else if (job == 1) {
        softmax_body<512>(gs + OFF_S2 + (size_t)b * LCPD * LENZ,
                          gs + OFF_WB2 + (size_t)b * LENZ, LCPD, 16, yc * 16, colsum);
    } else if (job == 2) {
        softmax_body<128>(gs + OFF_S3 + (size_t)b * LENZ * LCPD,
                          gs + OFF_WB3 + (size_t)b * LCPD, LENZ, 64, yc * 64, colsum);
    } else {
        softmax_body<512>(gs + OFF_S4 + (size_t)b * LCPD * LENZ,
                          gs + OFF_WB4 + (size_t)b * LENZ, LCPD, 16, yc * 16, colsum);
    }
}

// ==================== weighted feature sums ====================
__global__ void wfeat_small2(const float* __restrict__ subs, const float* __restrict__ prod) {
    int b = blockIdx.x, kc = blockIdx.y, src = blockIdx.z;
    const float* X = src ? prod : subs;
    const float* wbar = g_scratch + (src ? OFF_WB3 : OFF_WB1) + (size_t)b * LCPD;
    float* xb = g_scratch + (src ? OFF_XB3 : OFF_XB1) + (size_t)b * DCPD;
    __shared__ float w[32];
    if (threadIdx.x < 32) w[threadIdx.x] = wbar[kc * 32 + threadIdx.x];
    __syncthreads();
    int d = threadIdx.x;
    float acc = 0.f;
    const float* xp = X + ((size_t)b * LCPD + kc * 32) * DCPD + d;
#pragma unroll 8
    for (int k = 0; k < 32; k++) acc += w[k] * xp[(size_t)k * DCPD];
    atomicAdd(&xb[d], acc);
}

__global__ void wfeat_enz(const float* __restrict__ X) {
    int b = blockIdx.x;
    int d = blockIdx.y * 256 + threadIdx.x;
    const float* w2g = g_scratch + OFF_WB2 + (size_t)b * LENZ;
    const float* w4g = g_scratch + OFF_WB4 + (size_t)b * LENZ;
    __shared__ float s2[LENZ], s4[LENZ];
    for (int i = threadIdx.x; i < LENZ; i += 256) {
        s2[i] = w2g[i];
        s4[i] = w4g[i];
    }
    __syncthreads();
    float a2 = 0.f, a4 = 0.f;
    const float* xp = X + (size_t)b * LENZ * DENZ + d;
#pragma unroll 8
    for (int k = 0; k < LENZ; k++) {
        float x = xp[(size_t)k * DENZ];
        a2 += s2[k] * x;
        a4 += s4[k] * x;
    }
    g_scratch[OFF_XB2 + (size_t)b * DENZ + d] = a2;
    g_scratch[OFF_XB4 + (size_t)b * DENZ + d] = a4;
}

// ==================== final GEMVs ====================
__global__ __launch_bounds__(512) void final_out(
        const float* __restrict__ Wv0, const float* __restrict__ bv0,
        const float* __restrict__ Wv1, const float* __restrict__ bv1,
        const float* __restrict__ Wv2, const float* __restrict__ bv2,
        const float* __restrict__ Wv3, const float* __restrict__ bv3,
        float* __restrict__ out) {
    int b = blockIdx.x, p = blockIdx.y, d = threadIdx.x;
    const float* xb; const float* Wv; const float* bv; int Kd;
    if (p == 0)      { xb = g_scratch + OFF_XB1 + (size_t)b * DCPD; Wv = Wv0; bv = bv0; Kd = DCPD; }
    else if (p == 1) { xb = g_scratch + OFF_XB2 + (size_t)b * DENZ; Wv = Wv1; bv = bv1; Kd = DENZ; }
    else if (p == 2) { xb = g_scratch + OFF_XB3 + (size_t)b * DCPD; Wv = Wv2; bv = bv2; Kd = DCPD; }
    else             { xb = g_scratch + OFF_XB4 + (size_t)b * DENZ; Wv = Wv3; bv = bv3; Kd = DENZ; }

    __shared__ float xs[DENZ];
    for (int i = threadIdx.x; i < Kd; i += 512) xs[i] = xb[i];
    __syncthreads();

    float acc = bv[d];
#pragma unroll 4
    for (int j = 0; j < Kd; j++) acc += xs[j] * Wv[(size_t)j * DOUT + d];
    out[(size_t)b * 2048 + p * 512 + d] = acc;
}

// ==================== launch ====================
extern "C" void kernel_launch(void* const* d_in, const int* in_sizes, int n_in,
                              void* d_out, int out_size) {
    const float* enz   = (const float*)d_in[0];
    const float* subs  = (const float*)d_in[1];
    const float* prod  = (const float*)d_in[2];
    const float* IW    = (const float*)d_in[6];
    const float* enz_Wq = (const float*)d_in[7];
    const float* enz_bq = (const float*)d_in[8];
    const float* enz_Wk = (const float*)d_in[9];
    const float* enz_bk = (const float*)d_in[10];
    const float* enz_Wv = (const float*)d_in[11];
    const float* enz_bv = (const float*)d_in[12];
    const float* sub_Wq = (const float*)d_in[13];
    const float* sub_bq = (const float*)d_in[14];
    const float* sub_Wk = (const float*)d_in[15];
    const float* sub_bk = (const float*)d_in[16];
    const float* sub_Wv = (const float*)d_in[17];
    const float* sub_bv = (const float*)d_in[18];
    const float* prod_Wq = (const float*)d_in[19];
    const float* prod_bq = (const float*)d_in[20];
    const float* prod_Wk = (const float*)d_in[21];
    const float* prod_bk = (const float*)d_in[22];
    const float* prod_Wv = (const float*)d_in[23];
    const float* prod_bv = (const float*)d_in[24];
    float* out = (float*)d_out;

    static float* gs = nullptr;
    static __nv_bfloat16 *Ah = nullptr, *Al = nullptr, *Wht = nullptr, *Wlt = nullptr;
    static __nv_bfloat16 *X2h = nullptr, *X2l = nullptr, *W2h = nullptr, *W2l = nullptr;
    static __nv_bfloat16 *QKh = nullptr, *QKl = nullptr, *Ch = nullptr, *Cl = nullptr;
    static bool inited = false;
    if (!inited) {
        void* p = nullptr;
        cudaGetSymbolAddress(&p, g_scratch);  gs = (float*)p;
        cudaGetSymbolAddress(&p, g_Ah);       Ah = (__nv_bfloat16*)p;
        cudaGetSymbolAddress(&p, g_Al);       Al = (__nv_bfloat16*)p;
        cudaGetSymbolAddress(&p, g_Wht);      Wht = (__nv_bfloat16*)p;
        cudaGetSymbolAddress(&p, g_Wlt);      Wlt = (__nv_bfloat16*)p;
        cudaGetSymbolAddress(&p, g_X2h);      X2h = (__nv_bfloat16*)p;
        cudaGetSymbolAddress(&p, g_X2l);      X2l = (__nv_bfloat16*)p;
        cudaGetSymbolAddress(&p, g_W2h);      W2h = (__nv_bfloat16*)p;
        cudaGetSymbolAddress(&p, g_W2l);      W2l = (__nv_bfloat16*)p;
        cudaGetSymbolAddress(&p, g_QKh);      QKh = (__nv_bfloat16*)p;
        cudaGetSymbolAddress(&p, g_QKl);      QKl = (__nv_bfloat16*)p;
        cudaGetSymbolAddress(&p, g_Ch);       Ch = (__nv_bfloat16*)p;
        cudaGetSymbolAddress(&p, g_Cl);       Cl = (__nv_bfloat16*)p;
        cudaFuncSetAttribute(hmma_nn_kernel,
                             cudaFuncAttributeMaxDynamicSharedMemorySize, SMEM_MMA_BYTES);
        cudaFuncSetAttribute(score_kernel,
                             cudaFuncAttributeMaxDynamicSharedMemorySize, SMEM_MMA_BYTES);
        inited = true;
    }

    // #1: merged head (all conversions + biases + zeroing)
    head_kernel<<<HB9, 256>>>(enz, subs, prod,
                              enz_Wq, enz_bq, enz_Wk, enz_bk,
                              sub_Wq, sub_bq, sub_Wk, sub_bk,
                              prod_Wq, prod_bq, prod_Wk, prod_bk);

    // #2, #3: cpd projections on HMMA
    hmma_nn_kernel<<<dim3(1024 / 128, (NB * LCPD) / 128), 256, SMEM_MMA_BYTES>>>(
        X2h, X2l, W2h, W2l, gs + OFF_BCS, Ch, Cl, DCPD, 1024);
    hmma_nn_kernel<<<dim3(1024 / 128, (NB * LCPD) / 128), 256, SMEM_MMA_BYTES>>>(
        X2h + N_CPD, X2l + N_CPD, W2h + N_W2, W2l + N_W2,
        gs + OFF_BCP, Ch + CPOFF, Cl + CPOFF, DCPD, 1024);

    // #4: BIG projection (positioned 4th for ncu capture)
    hmma_nn_kernel<<<dim3(1536 / 128, (NB * LENZ) / 128), 256, SMEM_MMA_BYTES>>>(
        Ah, Al, Wht, Wlt, gs + OFF_BCE, QKh, QKl, DENZ, 1536);

    // #5: all four score GEMMs
    score_kernel<<<dim3(4, 1, 128), 256, SMEM_MMA_BYTES>>>(IW);

    // #6: all four softmax+mean reductions
    softmax_all<<<dim3(NB, 8, 4), 256>>>();

    // #7, #8: weighted feature sums
    wfeat_small2<<<dim3(NB, 4, 2), 256>>>(subs, prod);
    wfeat_enz<<<dim3(NB, DENZ / 256), 256>>>(enz);

    // #9: final GEMVs
    final_out<<<dim3(NB, 4), 512>>>(enz_Wv, enz_bv,
                                    sub_Wv, sub_bv,
                                    enz_Wv, enz_bv,
                                    prod_Wv, prod_bv,
                                    out);
}

// round 15
// speedup vs baseline: 1.0022x; 1.0022x over previous
#include <cuda_runtime.h>
#include <cuda_bf16.h>
#include <math.h>
#include <stdint.h>

// Problem dims
#define NB    32
#define LENZ  512
#define LCPD  128
#define DENZ  1280
#define DCPD  256
#define DOUT  512

static constexpr float INV_SCALE = 0.04419417382415922f; // 1/sqrt(512)

// ==================== scratch (fp32) ====================
static constexpr size_t SZ_S_BIG = (size_t)NB * LENZ * LCPD;
static constexpr size_t SZ_BCE   = 1536;
static constexpr size_t SZ_BCS   = 1024;
static constexpr size_t SZ_BCP   = 1024;
static constexpr size_t SZ_WB1   = (size_t)NB * LCPD;
static constexpr size_t SZ_WB2   = (size_t)NB * LENZ;
static constexpr size_t SZ_WB3   = (size_t)NB * LCPD;
static constexpr size_t SZ_WB4   = (size_t)NB * LENZ;
static constexpr size_t SZ_XB1   = (size_t)NB * DCPD;
static constexpr size_t SZ_XB3   = (size_t)NB * DCPD;
static constexpr size_t SZ_XB2   = (size_t)NB * DENZ;
static constexpr size_t SZ_XB4   = (size_t)NB * DENZ;

static constexpr size_t OFF_S1    = 0;
static constexpr size_t OFF_S2    = OFF_S1 + SZ_S_BIG;
static constexpr size_t OFF_S3    = OFF_S2 + SZ_S_BIG;
static constexpr size_t OFF_S4    = OFF_S3 + SZ_S_BIG;
static constexpr size_t OFF_BCE   = OFF_S4 + SZ_S_BIG;
static constexpr size_t OFF_BCS   = OFF_BCE + SZ_BCE;
static constexpr size_t OFF_BCP   = OFF_BCS + SZ_BCS;
static constexpr size_t OFF_WB1   = OFF_BCP + SZ_BCP;
static constexpr size_t OFF_WB2   = OFF_WB1 + SZ_WB1;
static constexpr size_t OFF_WB3   = OFF_WB2 + SZ_WB2;
static constexpr size_t OFF_WB4   = OFF_WB3 + SZ_WB3;
static constexpr size_t OFF_XB1   = OFF_WB4 + SZ_WB4;
static constexpr size_t OFF_XB3   = OFF_XB1 + SZ_XB1;
static constexpr size_t OFF_XB2   = OFF_XB3 + SZ_XB3;
static constexpr size_t OFF_XB4   = OFF_XB2 + SZ_XB2;
static constexpr size_t SCRATCH_TOTAL = OFF_XB4 + SZ_XB4;
static constexpr size_t ZERO_LEN = SZ_WB1 + SZ_WB2 + SZ_WB3 + SZ_WB4 + SZ_XB1 + SZ_XB3; // 57344
static_assert(OFF_XB1 == OFF_WB1 + SZ_WB1 + SZ_WB2 + SZ_WB3 + SZ_WB4, "zero region contiguity");
static_assert(OFF_XB3 == OFF_XB1 + SZ_XB1, "zero region contiguity");

static __device__ float g_scratch[SCRATCH_TOTAL];

// bf16 hi/lo operands
static __device__ __align__(16) __nv_bfloat16 g_Ah[(size_t)NB * LENZ * DENZ];
static __device__ __align__(16) __nv_bfloat16 g_Al[(size_t)NB * LENZ * DENZ];
static __device__ __align__(16) __nv_bfloat16 g_Wht[(size_t)1536 * DENZ];   // [1536,1280]
static __device__ __align__(16) __nv_bfloat16 g_Wlt[(size_t)1536 * DENZ];
static __device__ __align__(16) __nv_bfloat16 g_X2h[(size_t)2 * NB * LCPD * DCPD]; // subs|prod
static __device__ __align__(16) __nv_bfloat16 g_X2l[(size_t)2 * NB * LCPD * DCPD];
static __device__ __align__(16) __nv_bfloat16 g_W2h[(size_t)2 * 1024 * DCPD];      // [1024,256] x2
static __device__ __align__(16) __nv_bfloat16 g_W2l[(size_t)2 * 1024 * DCPD];
// projection outputs as bf16 hi/lo
static __device__ __align__(16) __nv_bfloat16 g_QKh[(size_t)NB * LENZ * 1536];
static __device__ __align__(16) __nv_bfloat16 g_QKl[(size_t)NB * LENZ * 1536];
static __device__ __align__(16) __nv_bfloat16 g_Ch[(size_t)2 * NB * LCPD * 1024];  // sub|prod
static __device__ __align__(16) __nv_bfloat16 g_Cl[(size_t)2 * NB * LCPD * 1024];

static constexpr size_t CPOFF = (size_t)NB * LCPD * 1024;  // prod offset in g_Ch/g_Cl

// ==================== merged head kernel ====================
static constexpr size_t N_ENZ  = (size_t)NB * LENZ * DENZ;
static constexpr size_t N_W    = (size_t)1536 * DENZ;
static constexpr size_t N_CPD  = (size_t)NB * LCPD * DCPD;
static constexpr size_t N_W2   = (size_t)1024 * DCPD;

static constexpr int HB0 = (int)(N_ENZ / 1024);
static constexpr int HB1 = HB0 + (int)(N_W / 1024);
static constexpr int HB2 = HB1 + (int)(N_CPD / 1024);
static constexpr int HB3 = HB2 + (int)(N_CPD / 1024);
static constexpr int HB4 = HB3 + (int)(N_W2 / 1024);
static constexpr int HB5 = HB4 + (int)(N_W2 / 1024);
static constexpr int HB6 = HB5 + 6;
static constexpr int HB7 = HB6 + 4;
static constexpr int HB8 = HB7 + 4;
static constexpr int HB9 = HB8 + (int)(ZERO_LEN / 1024);
static_assert((size_t)HB0 * 1024 == N_ENZ, "convA range");
static_assert((size_t)(HB1 - HB0) * 1024 == N_W, "convW range");
static_assert((size_t)(HB3 - HB2) * 1024 == N_CPD, "convX range");
static_assert((size_t)(HB5 - HB4) * 1024 == N_W2, "convW2 range");
static_assert((size_t)(HB9 - HB8) * 1024 == ZERO_LEN, "zero range");

__device__ __forceinline__ void split4_store(const float* xs, __nv_bfloat16* H,
                                             __nv_bfloat16* L, size_t i) {
    unsigned short hs[4], ls[4];
#pragma unroll
    for (int j = 0; j < 4; j++) {
        __nv_bfloat16 h = __float2bfloat16(xs[j]);
        hs[j] = __bfloat16_as_ushort(h);
        ls[j] = __bfloat16_as_ushort(__float2bfloat16(xs[j] - __bfloat162float(h)));
    }
    *(uint2*)(H + i) = make_uint2((uint32_t)hs[0] | ((uint32_t)hs[1] << 16),
                                  (uint32_t)hs[2] | ((uint32_t)hs[3] << 16));
    *(uint2*)(L + i) = make_uint2((uint32_t)ls[0] | ((uint32_t)ls[1] << 16),
                                  (uint32_t)ls[2] | ((uint32_t)ls[3] << 16));
}

__global__ void head_kernel(const float* __restrict__ enz,
                            const float* __restrict__ subs,
                            const float* __restrict__ prod,
                            const float* __restrict__ enz_Wq, const float* __restrict__ enz_bq,
                            const float* __restrict__ enz_Wk, const float* __restrict__ enz_bk,
                            const float* __restrict__ sub_Wq, const float* __restrict__ sub_bq,
                            const float* __restrict__ sub_Wk, const float* __restrict__ sub_bk,
                            const float* __restrict__ prod_Wq, const float* __restrict__ prod_bq,
                            const float* __restrict__ prod_Wk, const float* __restrict__ prod_bk) {
    const int blk = blockIdx.x;
    const int tid = threadIdx.x;

    if (blk < HB0) {
        size_t i = ((size_t)blk * 256 + tid) * 4;
        float4 v = *(const float4*)(enz + i);
        float xs[4] = {v.x, v.y, v.z, v.w};
        split4_store(xs, g_Ah, g_Al, i);
    } else if (blk < HB1) {
        size_t flat = ((size_t)(blk - HB0) * 256 + tid) * 4;
        int n = (int)(flat / DENZ), k = (int)(flat % DENZ);
        const float* src; int nn = n;
        if (n < 512)       src = enz_Wq;
        else if (n < 1024) { src = sub_Wk;  nn = n - 512; }
        else               { src = prod_Wk; nn = n - 1024; }
        float xs[4];
#pragma unroll
        for (int j = 0; j < 4; j++) xs[j] = src[(size_t)(k + j) * 512 + nn];
        split4_store(xs, g_Wht, g_Wlt, flat);
    } else if (blk < HB2) {
        size_t i = ((size_t)(blk - HB1) * 256 + tid) * 4;
        float4 v = *(const float4*)(subs + i);
        float xs[4] = {v.x, v.y, v.z, v.w};
        split4_store(xs, g_X2h, g_X2l, i);
    } else if (blk < HB3) {
        size_t i = ((size_t)(blk - HB2) * 256 + tid) * 4;
        float4 v = *(const float4*)(prod + i);
        float xs[4] = {v.x, v.y, v.z, v.w};
        split4_store(xs, g_X2h + N_CPD, g_X2l + N_CPD, i);
    } else if (blk < HB4) {
        size_t flat = ((size_t)(blk - HB3) * 256 + tid) * 4;
        int n = (int)(flat / DCPD), k = (int)(flat % DCPD);
        const float* src = (n < 512) ? enz_Wk : sub_Wq;
        int nn = (n < 512) ? n : n - 512;
        float xs[4];
#pragma unroll
        for (int j = 0; j < 4; j++) xs[j] = src[(size_t)(k + j) * 512 + nn];
        split4_store(xs, g_W2h, g_W2l, flat);
    } else if (blk < HB5) {
        size_t flat = ((size_t)(blk - HB4) * 256 + tid) * 4;
        int n = (int)(flat / DCPD), k = (int)(flat % DCPD);
        const float* src = (n < 512) ? enz_Wk : prod_Wq;
        int nn = (n < 512) ? n : n - 512;
        float xs[4];
#pragma unroll
        for (int j = 0; j < 4; j++) xs[j] = src[(size_t)(k + j) * 512 + nn];
        split4_store(xs, g_W2h + N_W2, g_W2l + N_W2, flat);
    } else if (blk < HB6) {
        int c = (blk - HB5) * 256 + tid;
        if (c < 1536) {
            float v;
            if (c < 512)       v = enz_bq[c];
            else if (c < 1024) v = sub_bk[c - 512];
            else               v = prod_bk[c - 1024];
            g_scratch[OFF_BCE + c] = v;
        }
    } else if (blk < HB7) {
        int c = (blk - HB6) * 256 + tid;
        if (c < 1024)
            g_scratch[OFF_BCS + c] = (c < 512) ? enz_bk[c] : sub_bq[c - 512];
    } else if (blk < HB8) {
        int c = (blk - HB7) * 256 + tid;
        if (c < 1024)
            g_scratch[OFF_BCP + c] = (c < 512) ? enz_bk[c] : prod_bq[c - 512];
    } else if (blk < HB9) {
        size_t i = ((size_t)(blk - HB8) * 256 + tid) * 4;
        if (i < ZERO_LEN)
            *(float4*)&g_scratch[OFF_WB1 + i] = make_float4(0.f, 0.f, 0.f, 0.f);
    }
}

// ==================== HMMA helpers ====================
#define MMA_BF16(d, a, b) \
    asm volatile("mma.sync.aligned.m16n8k16.row.col.f32.bf16.bf16.f32 " \
                 "{%0,%1,%2,%3}, {%4,%5,%6,%7}, {%8,%9}, {%0,%1,%2,%3};" \
                 : "+f"((d)[0]), "+f"((d)[1]), "+f"((d)[2]), "+f"((d)[3]) \
                 : "r"((a)[0]), "r"((a)[1]), "r"((a)[2]), "r"((a)[3]), \
                   "r"((b)[0]), "r"((b)[1]))

#define LDSM_X4(r0, r1, r2, r3, addr) \
    asm volatile("ldmatrix.sync.aligned.m8n8.x4.shared.b16 {%0,%1,%2,%3}, [%4];" \
                 : "=r"(r0), "=r"(r1), "=r"(r2), "=r"(r3) : "r"(addr))

// cp.async: L2 -> smem, 16B, bypasses L1 and register file (sm_80+ baseline PTX)
#define CP_ASYNC16(smem_u32, gptr) \
    asm volatile("cp.async.cg.shared.global [%0], [%1], 16;" \
                 :: "r"(smem_u32), "l"(gptr) : "memory")
#define CP_COMMIT() asm volatile("cp.async.commit_group;" ::: "memory")
#define CP_WAIT0()  asm volatile("cp.async.wait_group 0;" ::: "memory")
#define CP_WAIT1()  asm volatile("cp.async.wait_group 1;" ::: "memory")

__device__ __forceinline__ uint32_t smem_u32_of(const void* p) {
    uint32_t a;
    asm("{ .reg .u64 t; cvta.to.shared.u64 t, %1; cvt.u32.u64 %0, t; }" : "=r"(a) : "l"(p));
    return a;
}

__device__ __forceinline__ uint32_t pack_hi2(float v0, float v1, uint32_t& lo_out) {
    __nv_bfloat16 h0 = __float2bfloat16(v0);
    __nv_bfloat16 h1 = __float2bfloat16(v1);
    __nv_bfloat16 l0 = __float2bfloat16(v0 - __bfloat162float(h0));
    __nv_bfloat16 l1 = __float2bfloat16(v1 - __bfloat162float(h1));
    lo_out = (uint32_t)__bfloat16_as_ushort(l0) | ((uint32_t)__bfloat16_as_ushort(l1) << 16);
    return (uint32_t)__bfloat16_as_ushort(h0) | ((uint32_t)__bfloat16_as_ushort(h1) << 16);
}

static constexpr int KCH = 32;
static constexpr int ROW_W = 20;                // 16 data words + 4 pad (80B rows, 16B-aligned)
static constexpr int TILE_W = 128 * ROW_W;      // 2560 words
static constexpr int STAGE_W = 4 * TILE_W;
static constexpr int NSTAGE = 3;                // 3-stage ring -> single barrier per chunk
static constexpr int SMEM_MMA_BYTES = NSTAGE * STAGE_W * 4;  // 122880
static_assert((ROW_W * 4) % 16 == 0, "row stride must be 16B-aligned for cp.async");

// Fill one stage: each thread issues 8 cp.async of 16B.
__device__ __forceinline__ void fill_stage(uint32_t st_base, int tid,
                                           const __nv_bfloat16* Ah, const __nv_bfloat16* Al,
                                           const __nv_bfloat16* Bh, const __nv_bfloat16* Bl,
                                           int bm, int bn, int lda, int ldb, int k0) {
#pragma unroll
    for (int i = 0; i < 2; i++) {
        int u = tid + i * 256;
        int r = u >> 2, c16 = u & 3;
        uint32_t so = st_base + (uint32_t)(r * ROW_W + c16 * 4) * 4;
        size_t ga = (size_t)(bm + r) * lda + k0 + c16 * 8;
        size_t gb = (size_t)(bn + r) * ldb + k0 + c16 * 8;
        CP_ASYNC16(so + 0 * TILE_W * 4, Ah + ga);
        CP_ASYNC16(so + 1 * TILE_W * 4, Al + ga);
        CP_ASYNC16(so + 2 * TILE_W * 4, Bh + gb);
        CP_ASYNC16(so + 3 * TILE_W * 4, Bl + gb);
    }
}

// Shared 3-stage mainloop body (fill AFTER barrier; one barrier per chunk).
#define HMMA_MAINLOOP(NCHUNK_, Ah_, Al_, Bh_, Bl_, lda_, ldb_)                               \
    fill_stage(smem0, tid, Ah_, Al_, Bh_, Bl_, bm, bn, lda_, ldb_, 0);                       \
    CP_COMMIT();                                                                             \
    fill_stage(smem0 + STAGE_W * 4, tid, Ah_, Al_, Bh_, Bl_, bm, bn, lda_, ldb_, KCH);       \
    CP_COMMIT();                                                                             \
    for (int ch = 0; ch < (NCHUNK_); ch++) {                                                 \
        if (ch == (NCHUNK_) - 1) { CP_WAIT0(); } else { CP_WAIT1(); }                        \
        __syncthreads();                                                                     \
        if (ch + 2 < (NCHUNK_)) {                                                            \
            int st = (ch + 2) % NSTAGE;                                                      \
            fill_stage(smem0 + (st * STAGE_W) * 4, tid, Ah_, Al_, Bh_, Bl_,                  \
                       bm, bn, lda_, ldb_, (ch + 2) * KCH);                                  \
            CP_COMMIT();                                                                     \
        }                                                                                    \
        const uint32_t stAh = smem0 + ((ch % NSTAGE) * STAGE_W) * 4;                         \
        const uint32_t stAl = stAh + TILE_W * 4;                                             \
        const uint32_t stBh = stAh + 2 * TILE_W * 4;                                         \
        const uint32_t stBl = stAh + 3 * TILE_W * 4;                                         \
        _Pragma("unroll")                                                                    \
        for (int ks = 0; ks < 2; ks++) {                                                     \
            const int kw = ks * 8;                                                           \
            uint32_t ah[4][4], al[4][4], bh[4][2], bl[4][2];                                 \
            _Pragma("unroll")                                                                \
            for (int mi = 0; mi < 4; mi++) {                                                 \
                uint32_t wo = (uint32_t)((wm * 64 + mi * 16 + a_row_off) * ROW_W             \
                                         + kw + a_kh) * 4;                                   \
                LDSM_X4(ah[mi][0], ah[mi][1], ah[mi][2], ah[mi][3], stAh + wo);              \
                LDSM_X4(al[mi][0], al[mi][1], al[mi][2], al[mi][3], stAl + wo);              \
            }                                                                                \
            _Pragma("unroll")                                                                \
            for (int p = 0; p < 2; p++) {                                                    \
                uint32_t wo = (uint32_t)((wn * 32 + p * 16 + b_row_off) * ROW_W              \
                                         + kw + b_kh) * 4;                                   \
                uint32_t t0, t1, t2, t3;                                                     \
                LDSM_X4(t0, t1, t2, t3, stBh + wo);                                          \
                bh[2 * p][0] = t0; bh[2 * p][1] = t1;                                        \
                bh[2 * p + 1][0] = t2; bh[2 * p + 1][1] = t3;                                \
                LDSM_X4(t0, t1, t2, t3, stBl + wo);                                          \
                bl[2 * p][0] = t0; bl[2 * p][1] = t1;                                        \
                bl[2 * p + 1][0] = t2; bl[2 * p + 1][1] = t3;                                \
            }                                                                                \
            _Pragma("unroll")                                                                \
            for (int mi = 0; mi < 4; mi++)                                                   \
                _Pragma("unroll")                                                            \
                for (int ni = 0; ni < 4; ni++) {                                             \
                    MMA_BF16(acc[mi][ni], ah[mi], bh[ni]);                                   \
                    MMA_BF16(acc[mi][ni], ah[mi], bl[ni]);                                   \
                    MMA_BF16(acc[mi][ni], al[mi], bh[ni]);                                   \
                }                                                                            \
        }                                                                                    \
    }

// ==================== generic HMMA NN projection (bf16 hi/lo out) ====================
__global__ __launch_bounds__(256, 1)
void hmma_nn_kernel(const __nv_bfloat16* __restrict__ Ah, const __nv_bfloat16* __restrict__ Al,
                    const __nv_bfloat16* __restrict__ Bh, const __nv_bfloat16* __restrict__ Bl,
                    const float* __restrict__ bias,
                    __nv_bfloat16* __restrict__ Ch, __nv_bfloat16* __restrict__ Cl,
                    int K, int ldc) {
    extern __shared__ uint32_t smw[];
    const int tid  = threadIdx.x;
    const int lane = tid & 31;
    const int w    = tid >> 5;
    const int wm   = w & 1;
    const int wn   = w >> 1;
    const int r4   = lane >> 2;
    const int tg   = lane & 3;
    const int bm   = blockIdx.y * 128;
    const int bn   = blockIdx.x * 128;
    const int NCHUNK = K / KCH;
    const uint32_t smem0 = smem_u32_of(smw);

    const int lrow = lane & 7, grp = lane >> 3;
    const int a_row_off = ((grp & 1) << 3) + lrow;
    const int a_kh = (grp >> 1) * 4;
    const int b_row_off = ((grp >> 1) << 3) + lrow;
    const int b_kh = (grp & 1) * 4;

    float acc[4][4][4];
#pragma unroll
    for (int i = 0; i < 4; i++)
#pragma unroll
        for (int j = 0; j < 4; j++)
#pragma unroll
            for (int q = 0; q < 4; q++) acc[i][j][q] = 0.f;

    HMMA_MAINLOOP(NCHUNK, Ah, Al, Bh, Bl, K, K)

#pragma unroll
    for (int ni = 0; ni < 4; ni++) {
        int col = bn + wn * 32 + ni * 8 + tg * 2;
        float b0 = bias[col], b1 = bias[col + 1];
#pragma unroll
        for (int mi = 0; mi < 4; mi++) {
            int row0 = bm + wm * 64 + mi * 16 + r4;
            float v00 = acc[mi][ni][0] + b0, v01 = acc[mi][ni][1] + b1;
            float v10 = acc[mi][ni][2] + b0, v11 = acc[mi][ni][3] + b1;
            uint32_t lo0, lo1;
            uint32_t hi0 = pack_hi2(v00, v01, lo0);
            uint32_t hi1 = pack_hi2(v10, v11, lo1);
            size_t o0 = (size_t)row0 * ldc + col;
            size_t o1 = (size_t)(row0 + 8) * ldc + col;
            *(uint32_t*)(Ch + o0) = hi0;
            *(uint32_t*)(Cl + o0) = lo0;
            *(uint32_t*)(Ch + o1) = hi1;
            *(uint32_t*)(Cl + o1) = lo1;
        }
    }
}

// ==================== merged score GEMM (all 4 mats, one launch) ====================
__global__ __launch_bounds__(256, 1)
void score_kernel(const float* __restrict__ IW) {
    extern __shared__ uint32_t smw[];
    const int tid  = threadIdx.x;
    const int lane = tid & 31;
    const int w    = tid >> 5;
    const int wm   = w & 1;
    const int wn   = w >> 1;
    const int r4   = lane >> 2;
    const int tg   = lane & 3;
    const int z    = blockIdx.z;
    const int job  = z >> 5;
    const int b    = z & 31;
    const int tile = blockIdx.x;
    const int NCHUNK = DOUT / KCH;   // 16
    const uint32_t smem0 = smem_u32_of(smw);

    const int lrow = lane & 7, grp = lane >> 3;
    const int a_row_off = ((grp & 1) << 3) + lrow;
    const int a_kh = (grp >> 1) * 4;
    const int b_row_off = ((grp >> 1) << 3) + lrow;
    const int b_kh = (grp & 1) * 4;

    const size_t sQK = (size_t)LENZ * 1536;
    const size_t sCP = (size_t)LCPD * 1024;
    const size_t sIW = (size_t)LCPD * LENZ;

    const __nv_bfloat16 *Ah, *Al, *Bh, *Bl;
    int lda, ldb, M, N, biasMode;
    float* S;
    if (job == 0) {
        Ah = g_QKh; Al = g_QKl; lda = 1536;
        Bh = g_Ch;  Bl = g_Cl;  ldb = 1024;
        M = LENZ; N = LCPD; biasMode = 1; S = g_scratch + OFF_S1;
        Ah += (size_t)b * sQK; Al += (size_t)b * sQK;
        Bh += (size_t)b * sCP; Bl += (size_t)b * sCP;
    } else if (job == 1) {
        Ah = g_Ch + 512; Al = g_Cl + 512; lda = 1024;
        Bh = g_QKh + 512; Bl = g_QKl + 512; ldb = 1536;
        M = LCPD; N = LENZ; biasMode = 2; S = g_scratch + OFF_S2;
        Ah += (size_t)b * sCP; Al += (size_t)b * sCP;
        Bh += (size_t)b * sQK; Bl += (size_t)b * sQK;
    } else if (job == 2) {
        Ah = g_QKh; Al = g_QKl; lda = 1536;
        Bh = g_Ch + CPOFF; Bl = g_Cl + CPOFF; ldb = 1024;
        M = LENZ; N = LCPD; biasMode = 0; S = g_scratch + OFF_S3;
        Ah += (size_t)b * sQK; Al += (size_t)b * sQK;
        Bh += (size_t)b * sCP; Bl += (size_t)b * sCP;
    } else {
        Ah = g_Ch + CPOFF + 512; Al = g_Cl + CPOFF + 512; lda = 1024;
        Bh = g_QKh + 1024; Bl = g_QKl + 1024; ldb = 1536;
        M = LCPD; N = LENZ; biasMode = 0; S = g_scratch + OFF_S4;
        Ah += (size_t)b * sCP; Al += (size_t)b * sCP;
        Bh += (size_t)b * sQK; Bl += (size_t)b * sQK;
    }
    S += (size_t)b * (size_t)M * N;
    const float* bias = IW + (size_t)b * sIW;

    const int bm = (M == LENZ) ? tile * 128 : 0;
    const int bn = (M == LENZ) ? 0 : tile * 128;

    float acc[4][4][4];
#pragma unroll
    for (int i = 0; i < 4; i++)
#pragma unroll
        for (int j = 0; j < 4; j++)
#pragma unroll
            for (int q = 0; q < 4; q++) acc[i][j][q] = 0.f;

    HMMA_MAINLOOP(NCHUNK, Ah, Al, Bh, Bl, lda, ldb)

#pragma unroll
    for (int ni = 0; ni < 4; ni++) {
        int n0 = bn + wn * 32 + ni * 8 + tg * 2;
#pragma unroll
        for (int mi = 0; mi < 4; mi++) {
            int m0 = bm + wm * 64 + mi * 16 + r4;
#pragma unroll
            for (int half = 0; half < 2; half++) {
                int m = m0 + half * 8;
                float v0 = acc[mi][ni][half * 2 + 0] * INV_SCALE;
                float v1 = acc[mi][ni][half * 2 + 1] * INV_SCALE;
                if (biasMode == 1) {
                    v0 += bias[(size_t)n0 * M + m];
                    v1 += bias[(size_t)(n0 + 1) * M + m];
                } else if (biasMode == 2) {
                    v0 += bias[(size_t)m * N + n0];
                    v1 += bias[(size_t)m * N + n0 + 1];
                }
                *(float2*)&S[(size_t)m * N + n0] = make_float2(v0, v1);
            }
        }
    }
}

// ==================== merged softmax + mean -> wbar ====================
template <int LK>
__device__ __forceinline__ void softmax_body(const float* __restrict__ S, float* __restrict__ wbar,
                                             int Lq, int rowsPerBlock, int r0, float* colsum) {
    constexpr int EPL = LK / 32;
    int w = threadIdx.x / 32, lane = threadIdx.x % 32;
    int nw = blockDim.x / 32;

    for (int i = threadIdx.x; i < LK; i += blockDim.x) colsum[i] = 0.f;
    __syncthreads();

    for (int r = r0 + w; r < r0 + rowsPerBlock; r += nw) {
        const float* row = S + (size_t)r * LK;
        float v[EPL];
        float mx = -1e30f;
#pragma unroll
        for (int c = 0; c < EPL / 4; c++) {
            float4 t = *(const float4*)(row + c * 128 + lane * 4);
            v[c * 4 + 0] = t.x; v[c * 4 + 1] = t.y; v[c * 4 + 2] = t.z; v[c * 4 + 3] = t.w;
            mx = fmaxf(mx, fmaxf(fmaxf(t.x, t.y), fmaxf(t.z, t.w)));
        }
#pragma unroll
        for (int o = 16; o > 0; o >>= 1) mx = fmaxf(mx, __shfl_xor_sync(0xffffffffu, mx, o));
        float s = 0.f;
#pragma unroll
        for (int i = 0; i < EPL; i++) { v[i] = __expf(v[i] - mx); s += v[i]; }
#pragma unroll
        for (int o = 16; o > 0; o >>= 1) s += __shfl_xor_sync(0xffffffffu, s, o);
        float inv = 1.f / s;
#pragma unroll
        for (int c = 0; c < EPL / 4; c++)
#pragma unroll
            for (int j = 0; j < 4; j++)
                atomicAdd(&colsum[c * 128 + lane * 4 + j], v[c * 4 + j] * inv);
    }
    __syncthreads();
    float invLq = 1.f / (float)Lq;
    for (int i = threadIdx.x; i < LK; i += blockDim.x)
        atomicAdd(&wbar[i], colsum[i] * invLq);
}

__global__ void softmax_all(void) {
    __shared__ float colsum[512];
    int job = blockIdx.z;
    int b = blockIdx.x;
    int yc = blockIdx.y;
    float* gs = g_scratch;
    if (job == 0) {
        softmax_body<128>(gs + OFF_S1 + (size_t)b * LENZ * LCPD,
                          gs + OFF_WB1 + (size_t)b * LCPD, LENZ, 64, yc * 64, colsum);
    } else if (job == 1) {
        softmax_body<512>(gs + OFF_S2 + (size_t)b * LCPD * LENZ,
                          gs + OFF_WB2 + (size_t)b * LENZ, LCPD, 16, yc * 16, colsum);
    } else if (job == 2) {
        softmax_body<128>(gs + OFF_S3 + (size_t)b * LENZ * LCPD,
                          gs + OFF_WB3 + (size_t)b * LCPD, LENZ, 64, yc * 64, colsum);
    } else {
        softmax_body<512>(gs + OFF_S4 + (size_t)b * LCPD * LENZ,
                          gs + OFF_WB4 + (size_t)b * LENZ, LCPD, 16, yc * 16, colsum);
    }
}

// ==================== weighted feature sums ====================
__global__ void wfeat_small2(const float* __restrict__ subs, const float* __restrict__ prod) {
    int b = blockIdx.x, kc = blockIdx.y, src = blockIdx.z;
    const float* X = src ? prod : subs;
    const float* wbar = g_scratch + (src ? OFF_WB3 : OFF_WB1) + (size_t)b * LCPD;
    float* xb = g_scratch + (src ? OFF_XB3 : OFF_XB1) + (size_t)b * DCPD;
    __shared__ float w[32];
    if (threadIdx.x < 32) w[threadIdx.x] = wbar[kc * 32 + threadIdx.x];
    __syncthreads();
    int d = threadIdx.x;
    float acc = 0.f;
    const float* xp = X + ((size_t)b * LCPD + kc * 32) * DCPD + d;
#pragma unroll 8
    for (int k = 0; k < 32; k++) acc += w[k] * xp[(size_t)k * DCPD];
    atomicAdd(&xb[d], acc);
}

__global__ void wfeat_enz(const float* __restrict__ X) {
    int b = blockIdx.x;
    int d = blockIdx.y * 256 + threadIdx.x;
    const float* w2g = g_scratch + OFF_WB2 + (size_t)b * LENZ;
    const float* w4g = g_scratch + OFF_WB4 + (size_t)b * LENZ;
    __shared__ float s2[LENZ], s4[LENZ];
    for (int i = threadIdx.x; i < LENZ; i += 256) {
        s2[i] = w2g[i];
        s4[i] = w4g[i];
    }
    __syncthreads();
    float a2 = 0.f, a4 = 0.f;
    const float* xp = X + (size_t)b * LENZ * DENZ + d;
#pragma unroll 8
    for (int k = 0; k < LENZ; k++) {
        float x = xp[(size_t)k * DENZ];
        a2 += s2[k] * x;
        a4 += s4[k] * x;
    }
    g_scratch[OFF_XB2 + (size_t)b * DENZ + d] = a2;
    g_scratch[OFF_XB4 + (size_t)b * DENZ + d] = a4;
}

// ==================== final GEMVs ====================
__global__ __launch_bounds__(512) void final_out(
        const float* __restrict__ Wv0, const float* __restrict__ bv0,
        const float* __restrict__ Wv1, const float* __restrict__ bv1,
        const float* __restrict__ Wv2, const float* __restrict__ bv2,
        const float* __restrict__ Wv3, const float* __restrict__ bv3,
        float* __restrict__ out) {
    int b = blockIdx.x, p = blockIdx.y, d = threadIdx.x;
    const float* xb; const float* Wv; const float* bv; int Kd;
    if (p == 0)      { xb = g_scratch + OFF_XB1 + (size_t)b * DCPD; Wv = Wv0; bv = bv0; Kd = DCPD; }
    else if (p == 1) { xb = g_scratch + OFF_XB2 + (size_t)b * DENZ; Wv = Wv1; bv = bv1; Kd = DENZ; }
    else if (p == 2) { xb = g_scratch + OFF_XB3 + (size_t)b * DCPD; Wv = Wv2; bv = bv2; Kd = DCPD; }
    else             { xb = g_scratch + OFF_XB4 + (size_t)b * DENZ; Wv = Wv3; bv = bv3; Kd = DENZ; }

    __shared__ float xs[DENZ];
    for (int i = threadIdx.x; i < Kd; i += 512) xs[i] = xb[i];
    __syncthreads();

    float acc = bv[d];
#pragma unroll 4
    for (int j = 0; j < Kd; j++) acc += xs[j] * Wv[(size_t)j * DOUT + d];
    out[(size_t)b * 2048 + p * 512 + d] = acc;
}

// ==================== launch ====================
extern "C" void kernel_launch(void* const* d_in, const int* in_sizes, int n_in,
                              void* d_out, int out_size) {
    const float* enz   = (const float*)d_in[0];
    const float* subs  = (const float*)d_in[1];
    const float* prod  = (const float*)d_in[2];
    const float* IW    = (const float*)d_in[6];
    const float* enz_Wq = (const float*)d_in[7];
    const float* enz_bq = (const float*)d_in[8];
    const float* enz_Wk = (const float*)d_in[9];
    const float* enz_bk = (const float*)d_in[10];
    const float* enz_Wv = (const float*)d_in[11];
    const float* enz_bv = (const float*)d_in[12];
    const float* sub_Wq = (const float*)d_in[13];
    const float* sub_bq = (const float*)d_in[14];
    const float* sub_Wk = (const float*)d_in[15];
    const float* sub_bk = (const float*)d_in[16];
    const float* sub_Wv = (const float*)d_in[17];
    const float* sub_bv = (const float*)d_in[18];
    const float* prod_Wq = (const float*)d_in[19];
    const float* prod_bq = (const float*)d_in[20];
    const float* prod_Wk = (const float*)d_in[21];
    const float* prod_bk = (const float*)d_in[22];
    const float* prod_Wv = (const float*)d_in[23];
    const float* prod_bv = (const float*)d_in[24];
    float* out = (float*)d_out;

    static float* gs = nullptr;
    static __nv_bfloat16 *Ah = nullptr, *Al = nullptr, *Wht = nullptr, *Wlt = nullptr;
    static __nv_bfloat16 *X2h = nullptr, *X2l = nullptr, *W2h = nullptr, *W2l = nullptr;
    static __nv_bfloat16 *QKh = nullptr, *QKl = nullptr, *Ch = nullptr, *Cl = nullptr;
    static bool inited = false;
    if (!inited) {
        void* p = nullptr;
        cudaGetSymbolAddress(&p, g_scratch);  gs = (float*)p;
        cudaGetSymbolAddress(&p, g_Ah);       Ah = (__nv_bfloat16*)p;
        cudaGetSymbolAddress(&p, g_Al);       Al = (__nv_bfloat16*)p;
        cudaGetSymbolAddress(&p, g_Wht);      Wht = (__nv_bfloat16*)p;
        cudaGetSymbolAddress(&p, g_Wlt);      Wlt = (__nv_bfloat16*)p;
        cudaGetSymbolAddress(&p, g_X2h);      X2h = (__nv_bfloat16*)p;
        cudaGetSymbolAddress(&p, g_X2l);      X2l = (__nv_bfloat16*)p;
        cudaGetSymbolAddress(&p, g_W2h);      W2h = (__nv_bfloat16*)p;
        cudaGetSymbolAddress(&p, g_W2l);      W2l = (__nv_bfloat16*)p;
        cudaGetSymbolAddress(&p, g_QKh);      QKh = (__nv_bfloat16*)p;
        cudaGetSymbolAddress(&p, g_QKl);      QKl = (__nv_bfloat16*)p;
        cudaGetSymbolAddress(&p, g_Ch);       Ch = (__nv_bfloat16*)p;
        cudaGetSymbolAddress(&p, g_Cl);       Cl = (__nv_bfloat16*)p;
        cudaFuncSetAttribute(hmma_nn_kernel,
                             cudaFuncAttributeMaxDynamicSharedMemorySize, SMEM_MMA_BYTES);
        cudaFuncSetAttribute(score_kernel,
                             cudaFuncAttributeMaxDynamicSharedMemorySize, SMEM_MMA_BYTES);
        inited = true;
    }

    // #1: merged head (all conversions + biases + zeroing)
    head_kernel<<<HB9, 256>>>(enz, subs, prod,
                              enz_Wq, enz_bq, enz_Wk, enz_bk,
                              sub_Wq, sub_bq, sub_Wk, sub_bk,
                              prod_Wq, prod_bq, prod_Wk, prod_bk);

    // #2, #3: cpd projections on HMMA
    hmma_nn_kernel<<<dim3(1024 / 128, (NB * LCPD) / 128), 256, SMEM_MMA_BYTES>>>(
        X2h, X2l, W2h, W2l, gs + OFF_BCS, Ch, Cl, DCPD, 1024);
    hmma_nn_kernel<<<dim3(1024 / 128, (NB * LCPD) / 128), 256, SMEM_MMA_BYTES>>>(
        X2h + N_CPD, X2l + N_CPD, W2h + N_W2, W2l + N_W2,
        gs + OFF_BCP, Ch + CPOFF, Cl + CPOFF, DCPD, 1024);

    // #4: BIG projection (positioned 4th for ncu capture)
    hmma_nn_kernel<<<dim3(1536 / 128, (NB * LENZ) / 128), 256, SMEM_MMA_BYTES>>>(
        Ah, Al, Wht, Wlt, gs + OFF_BCE, QKh, QKl, DENZ, 1536);

    // #5: all four score GEMMs
    score_kernel<<<dim3(4, 1, 128), 256, SMEM_MMA_BYTES>>>(IW);

    // #6: all four softmax+mean reductions
    softmax_all<<<dim3(NB, 8, 4), 256>>>();

    // #7, #8: weighted feature sums
    wfeat_small2<<<dim3(NB, 4, 2), 256>>>(subs, prod);
    wfeat_enz<<<dim3(NB, DENZ / 256), 256>>>(enz);

    // #9: final GEMVs
    final_out<<<dim3(NB, 4), 512>>>(enz_Wv, enz_bv,
                                    sub_Wv, sub_bv,
                                    enz_Wv, enz_bv,
                                    prod_Wv, prod_bv,
                                    out);
}

// round 16
// speedup vs baseline: 1.1346x; 1.1321x over previous
#include <cuda_runtime.h>
#include <cuda_bf16.h>
#include <math.h>
#include <stdint.h>

// Problem dims
#define NB    32
#define LENZ  512
#define LCPD  128
#define DENZ  1280
#define DCPD  256
#define DOUT  512

static constexpr float INV_SCALE = 0.04419417382415922f; // 1/sqrt(512)

// ==================== scratch (fp32) ====================
static constexpr size_t SZ_S_BIG = (size_t)NB * LENZ * LCPD;
static constexpr size_t SZ_BCE   = 1536;
static constexpr size_t SZ_BCS   = 1024;
static constexpr size_t SZ_BCP   = 1024;
static constexpr size_t SZ_WB1   = (size_t)NB * LCPD;
static constexpr size_t SZ_WB2   = (size_t)NB * LENZ;
static constexpr size_t SZ_WB3   = (size_t)NB * LCPD;
static constexpr size_t SZ_WB4   = (size_t)NB * LENZ;
static constexpr size_t SZ_XB1   = (size_t)NB * DCPD;
static constexpr size_t SZ_XB3   = (size_t)NB * DCPD;
static constexpr size_t SZ_XB2   = (size_t)NB * DENZ;
static constexpr size_t SZ_XB4   = (size_t)NB * DENZ;

static constexpr size_t OFF_S1    = 0;
static constexpr size_t OFF_S2    = OFF_S1 + SZ_S_BIG;
static constexpr size_t OFF_S3    = OFF_S2 + SZ_S_BIG;
static constexpr size_t OFF_S4    = OFF_S3 + SZ_S_BIG;
static constexpr size_t OFF_BCE   = OFF_S4 + SZ_S_BIG;
static constexpr size_t OFF_BCS   = OFF_BCE + SZ_BCE;
static constexpr size_t OFF_BCP   = OFF_BCS + SZ_BCS;
static constexpr size_t OFF_WB1   = OFF_BCP + SZ_BCP;
static constexpr size_t OFF_WB2   = OFF_WB1 + SZ_WB1;
static constexpr size_t OFF_WB3   = OFF_WB2 + SZ_WB2;
static constexpr size_t OFF_WB4   = OFF_WB3 + SZ_WB3;
static constexpr size_t OFF_XB1   = OFF_WB4 + SZ_WB4;
static constexpr size_t OFF_XB3   = OFF_XB1 + SZ_XB1;
static constexpr size_t OFF_XB2   = OFF_XB3 + SZ_XB3;
static constexpr size_t OFF_XB4   = OFF_XB2 + SZ_XB2;
static constexpr size_t SCRATCH_TOTAL = OFF_XB4 + SZ_XB4;
static constexpr size_t ZERO_LEN = SZ_WB1 + SZ_WB2 + SZ_WB3 + SZ_WB4 + SZ_XB1 + SZ_XB3; // 57344
static_assert(OFF_XB1 == OFF_WB1 + SZ_WB1 + SZ_WB2 + SZ_WB3 + SZ_WB4, "zero region contiguity");
static_assert(OFF_XB3 == OFF_XB1 + SZ_XB1, "zero region contiguity");

static __device__ float g_scratch[SCRATCH_TOTAL];

// bf16 hi/lo operands
static __device__ __align__(16) __nv_bfloat16 g_Ah[(size_t)NB * LENZ * DENZ];
static __device__ __align__(16) __nv_bfloat16 g_Al[(size_t)NB * LENZ * DENZ];
static __device__ __align__(16) __nv_bfloat16 g_Wht[(size_t)1536 * DENZ];   // [1536,1280]
static __device__ __align__(16) __nv_bfloat16 g_Wlt[(size_t)1536 * DENZ];
static __device__ __align__(16) __nv_bfloat16 g_X2h[(size_t)2 * NB * LCPD * DCPD]; // subs|prod
static __device__ __align__(16) __nv_bfloat16 g_X2l[(size_t)2 * NB * LCPD * DCPD];
static __device__ __align__(16) __nv_bfloat16 g_W2h[(size_t)2 * 1024 * DCPD];      // [1024,256] x2
static __device__ __align__(16) __nv_bfloat16 g_W2l[(size_t)2 * 1024 * DCPD];
// projection outputs as bf16 hi/lo
static __device__ __align__(16) __nv_bfloat16 g_QKh[(size_t)NB * LENZ * 1536];
static __device__ __align__(16) __nv_bfloat16 g_QKl[(size_t)NB * LENZ * 1536];
static __device__ __align__(16) __nv_bfloat16 g_Ch[(size_t)2 * NB * LCPD * 1024];  // sub|prod
static __device__ __align__(16) __nv_bfloat16 g_Cl[(size_t)2 * NB * LCPD * 1024];

static constexpr size_t CPOFF = (size_t)NB * LCPD * 1024;  // prod offset in g_Ch/g_Cl

// ==================== merged head kernel ====================
static constexpr size_t N_ENZ  = (size_t)NB * LENZ * DENZ;
static constexpr size_t N_W    = (size_t)1536 * DENZ;
static constexpr size_t N_CPD  = (size_t)NB * LCPD * DCPD;
static constexpr size_t N_W2   = (size_t)1024 * DCPD;

static constexpr int HB0 = (int)(N_ENZ / 1024);
static constexpr int HB1 = HB0 + (int)(N_W / 1024);
static constexpr int HB2 = HB1 + (int)(N_CPD / 1024);
static constexpr int HB3 = HB2 + (int)(N_CPD / 1024);
static constexpr int HB4 = HB3 + (int)(N_W2 / 1024);
static constexpr int HB5 = HB4 + (int)(N_W2 / 1024);
static constexpr int HB6 = HB5 + 6;
static constexpr int HB7 = HB6 + 4;
static constexpr int HB8 = HB7 + 4;
static constexpr int HB9 = HB8 + (int)(ZERO_LEN / 1024);
static_assert((size_t)HB0 * 1024 == N_ENZ, "convA range");
static_assert((size_t)(HB1 - HB0) * 1024 == N_W, "convW range");
static_assert((size_t)(HB3 - HB2) * 1024 == N_CPD, "convX range");
static_assert((size_t)(HB5 - HB4) * 1024 == N_W2, "convW2 range");
static_assert((size_t)(HB9 - HB8) * 1024 == ZERO_LEN, "zero range");

__device__ __forceinline__ void split4_store(const float* xs, __nv_bfloat16* H,
                                             __nv_bfloat16* L, size_t i) {
    unsigned short hs[4], ls[4];
#pragma unroll
    for (int j = 0; j < 4; j++) {
        __nv_bfloat16 h = __float2bfloat16(xs[j]);
        hs[j] = __bfloat16_as_ushort(h);
        ls[j] = __bfloat16_as_ushort(__float2bfloat16(xs[j] - __bfloat162float(h)));
    }
    *(uint2*)(H + i) = make_uint2((uint32_t)hs[0] | ((uint32_t)hs[1] << 16),
                                  (uint32_t)hs[2] | ((uint32_t)hs[3] << 16));
    *(uint2*)(L + i) = make_uint2((uint32_t)ls[0] | ((uint32_t)ls[1] << 16),
                                  (uint32_t)ls[2] | ((uint32_t)ls[3] << 16));
}

__global__ void head_kernel(const float* __restrict__ enz,
                            const float* __restrict__ subs,
                            const float* __restrict__ prod,
                            const float* __restrict__ enz_Wq, const float* __restrict__ enz_bq,
                            const float* __restrict__ enz_Wk, const float* __restrict__ enz_bk,
                            const float* __restrict__ sub_Wq, const float* __restrict__ sub_bq,
                            const float* __restrict__ sub_Wk, const float* __restrict__ sub_bk,
                            const float* __restrict__ prod_Wq, const float* __restrict__ prod_bq,
                            const float* __restrict__ prod_Wk, const float* __restrict__ prod_bk) {
    const int blk = blockIdx.x;
    const int tid = threadIdx.x;

    if (blk < HB0) {
        size_t i = ((size_t)blk * 256 + tid) * 4;
        float4 v = *(const float4*)(enz + i);
        float xs[4] = {v.x, v.y, v.z, v.w};
        split4_store(xs, g_Ah, g_Al, i);
    } else if (blk < HB1) {
        size_t flat = ((size_t)(blk - HB0) * 256 + tid) * 4;
        int n = (int)(flat / DENZ), k = (int)(flat % DENZ);
        const float* src; int nn = n;
        if (n < 512)       src = enz_Wq;
        else if (n < 1024) { src = sub_Wk;  nn = n - 512; }
        else               { src = prod_Wk; nn = n - 1024; }
        float xs[4];
#pragma unroll
        for (int j = 0; j < 4; j++) xs[j] = src[(size_t)(k + j) * 512 + nn];
        split4_store(xs, g_Wht, g_Wlt, flat);
    } else if (blk < HB2) {
        size_t i = ((size_t)(blk - HB1) * 256 + tid) * 4;
        float4 v = *(const float4*)(subs + i);
        float xs[4] = {v.x, v.y, v.z, v.w};
        split4_store(xs, g_X2h, g_X2l, i);
    } else if (blk < HB3) {
        size_t i = ((size_t)(blk - HB2) * 256 + tid) * 4;
        float4 v = *(const float4*)(prod + i);
        float xs[4] = {v.x, v.y, v.z, v.w};
        split4_store(xs, g_X2h + N_CPD, g_X2l + N_CPD, i);
    } else if (blk < HB4) {
        size_t flat = ((size_t)(blk - HB3) * 256 + tid) * 4;
        int n = (int)(flat / DCPD), k = (int)(flat % DCPD);
        const float* src = (n < 512) ? enz_Wk : sub_Wq;
        int nn = (n < 512) ? n : n - 512;
        float xs[4];
#pragma unroll
        for (int j = 0; j < 4; j++) xs[j] = src[(size_t)(k + j) * 512 + nn];
        split4_store(xs, g_W2h, g_W2l, flat);
    } else if (blk < HB5) {
        size_t flat = ((size_t)(blk - HB4) * 256 + tid) * 4;
        int n = (int)(flat / DCPD), k = (int)(flat % DCPD);
        const float* src = (n < 512) ? enz_Wk : prod_Wq;
        int nn = (n < 512) ? n : n - 512;
        float xs[4];
#pragma unroll
        for (int j = 0; j < 4; j++) xs[j] = src[(size_t)(k + j) * 512 + nn];
        split4_store(xs, g_W2h + N_W2, g_W2l + N_W2, flat);
    } else if (blk < HB6) {
        int c = (blk - HB5) * 256 + tid;
        if (c < 1536) {
            float v;
            if (c < 512)       v = enz_bq[c];
            else if (c < 1024) v = sub_bk[c - 512];
            else               v = prod_bk[c - 1024];
            g_scratch[OFF_BCE + c] = v;
        }
    } else if (blk < HB7) {
        int c = (blk - HB6) * 256 + tid;
        if (c < 1024)
            g_scratch[OFF_BCS + c] = (c < 512) ? enz_bk[c] : sub_bq[c - 512];
    } else if (blk < HB8) {
        int c = (blk - HB7) * 256 + tid;
        if (c < 1024)
            g_scratch[OFF_BCP + c] = (c < 512) ? enz_bk[c] : prod_bq[c - 512];
    } else if (blk < HB9) {
        size_t i = ((size_t)(blk - HB8) * 256 + tid) * 4;
        if (i < ZERO_LEN)
            *(float4*)&g_scratch[OFF_WB1 + i] = make_float4(0.f, 0.f, 0.f, 0.f);
    }
}

// ==================== HMMA helpers ====================
#define MMA_BF16(d, a, b) \
    asm volatile("mma.sync.aligned.m16n8k16.row.col.f32.bf16.bf16.f32 " \
                 "{%0,%1,%2,%3}, {%4,%5,%6,%7}, {%8,%9}, {%0,%1,%2,%3};" \
                 : "+f"((d)[0]), "+f"((d)[1]), "+f"((d)[2]), "+f"((d)[3]) \
                 : "r"((a)[0]), "r"((a)[1]), "r"((a)[2]), "r"((a)[3]), \
                   "r"((b)[0]), "r"((b)[1]))

#define LDSM_X4(r0, r1, r2, r3, addr) \
    asm volatile("ldmatrix.sync.aligned.m8n8.x4.shared.b16 {%0,%1,%2,%3}, [%4];" \
                 : "=r"(r0), "=r"(r1), "=r"(r2), "=r"(r3) : "r"(addr))

// cp.async: L2 -> smem, 16B, bypasses L1 and the register file (sm_80+ baseline PTX)
#define CP_ASYNC16(smem_u32, gptr) \
    asm volatile("cp.async.cg.shared.global [%0], [%1], 16;" \
                 :: "r"(smem_u32), "l"(gptr) : "memory")
#define CP_COMMIT() asm volatile("cp.async.commit_group;" ::: "memory")
#define CP_WAIT0()  asm volatile("cp.async.wait_group 0;" ::: "memory")

__device__ __forceinline__ uint32_t smem_u32_of(const void* p) {
    uint32_t a;
    asm("{ .reg .u64 t; cvta.to.shared.u64 t, %1; cvt.u32.u64 %0, t; }" : "=r"(a) : "l"(p));
    return a;
}

__device__ __forceinline__ uint32_t pack_hi2(float v0, float v1, uint32_t& lo_out) {
    __nv_bfloat16 h0 = __float2bfloat16(v0);
    __nv_bfloat16 h1 = __float2bfloat16(v1);
    __nv_bfloat16 l0 = __float2bfloat16(v0 - __bfloat162float(h0));
    __nv_bfloat16 l1 = __float2bfloat16(v1 - __bfloat162float(h1));
    lo_out = (uint32_t)__bfloat16_as_ushort(l0) | ((uint32_t)__bfloat16_as_ushort(l1) << 16);
    return (uint32_t)__bfloat16_as_ushort(h0) | ((uint32_t)__bfloat16_as_ushort(h1) << 16);
}

static constexpr int KCH = 32;
static constexpr int ROW_W = 20;                // 16 data words + 4 pad (80B rows, 16B-aligned)
static constexpr int TILE_W = 128 * ROW_W;      // 2560 words (10KB)
static constexpr int STAGE_W = 4 * TILE_W;      // 40KB
static constexpr int NSTAGE = 2;                // 2 stages -> 80KB/CTA, 2 CTAs fit the carveout
static constexpr int SMEM_MMA_BYTES = NSTAGE * STAGE_W * 4;  // 81920
static_assert((ROW_W * 4) % 16 == 0, "row stride must be 16B-aligned for cp.async");

// Fill one stage: each thread issues 8 cp.async of 16B.
__device__ __forceinline__ void fill_stage(uint32_t st_base, int tid,
                                           const __nv_bfloat16* Ah, const __nv_bfloat16* Al,
                                           const __nv_bfloat16* Bh, const __nv_bfloat16* Bl,
                                           int bm, int bn, int lda, int ldb, int k0) {
#pragma unroll
    for (int i = 0; i < 2; i++) {
        int u = tid + i * 256;
        int r = u >> 2, c16 = u & 3;
        uint32_t so = st_base + (uint32_t)(r * ROW_W + c16 * 4) * 4;
        size_t ga = (size_t)(bm + r) * lda + k0 + c16 * 8;
        size_t gb = (size_t)(bn + r) * ldb + k0 + c16 * 8;
        CP_ASYNC16(so + 0 * TILE_W * 4, Ah + ga);
        CP_ASYNC16(so + 1 * TILE_W * 4, Al + ga);
        CP_ASYNC16(so + 2 * TILE_W * 4, Bh + gb);
        CP_ASYNC16(so + 3 * TILE_W * 4, Bl + gb);
    }
}

// 2-stage mainloop, ONE barrier per chunk, fill AFTER barrier.
// Register-lean inner structure: B fragments persist per ks (16 regs);
// A fragments live only inside each mi iteration (8 regs).
#define HMMA_MAINLOOP(NCHUNK_, Ah_, Al_, Bh_, Bl_, lda_, ldb_)                               \
    fill_stage(smem0, tid, Ah_, Al_, Bh_, Bl_, bm, bn, lda_, ldb_, 0);                       \
    CP_COMMIT();                                                                             \
    for (int ch = 0; ch < (NCHUNK_); ch++) {                                                 \
        CP_WAIT0();                                                                          \
        __syncthreads();                                                                     \
        if (ch + 1 < (NCHUNK_)) {                                                            \
            fill_stage(smem0 + (((ch & 1) ^ 1) * STAGE_W) * 4, tid, Ah_, Al_, Bh_, Bl_,      \
                       bm, bn, lda_, ldb_, (ch + 1) * KCH);                                  \
            CP_COMMIT();                                                                     \
        }                                                                                    \
        const uint32_t stAh = smem0 + ((ch & 1) * STAGE_W) * 4;                              \
        const uint32_t stAl = stAh + TILE_W * 4;                                             \
        const uint32_t stBh = stAh + 2 * TILE_W * 4;                                         \
        const uint32_t stBl = stAh + 3 * TILE_W * 4;                                         \
        _Pragma("unroll")                                                                    \
        for (int ks = 0; ks < 2; ks++) {                                                     \
            const int kw = ks * 8;                                                           \
            uint32_t bh[4][2], bl[4][2];                                                     \
            _Pragma("unroll")                                                                \
            for (int p = 0; p < 2; p++) {                                                    \
                uint32_t wo = (uint32_t)((wn * 32 + p * 16 + b_row_off) * ROW_W              \
                                         + kw + b_kh) * 4;                                   \
                uint32_t t0, t1, t2, t3;                                                     \
                LDSM_X4(t0, t1, t2, t3, stBh + wo);                                          \
                bh[2 * p][0] = t0; bh[2 * p][1] = t1;                                        \
                bh[2 * p + 1][0] = t2; bh[2 * p + 1][1] = t3;                                \
                LDSM_X4(t0, t1, t2, t3, stBl + wo);                                          \
                bl[2 * p][0] = t0; bl[2 * p][1] = t1;                                        \
                bl[2 * p + 1][0] = t2; bl[2 * p + 1][1] = t3;                                \
            }                                                                                \
            _Pragma("unroll")                                                                \
            for (int mi = 0; mi < 4; mi++) {                                                 \
                uint32_t ah[4], al[4];                                                       \
                uint32_t wo = (uint32_t)((wm * 64 + mi * 16 + a_row_off) * ROW_W             \
                                         + kw + a_kh) * 4;                                   \
                LDSM_X4(ah[0], ah[1], ah[2], ah[3], stAh + wo);                              \
                LDSM_X4(al[0], al[1], al[2], al[3], stAl + wo);                              \
                _Pragma("unroll")                                                            \
                for (int ni = 0; ni < 4; ni++) {                                             \
                    MMA_BF16(acc[mi][ni], ah, bh[ni]);                                       \
                    MMA_BF16(acc[mi][ni], ah, bl[ni]);                                       \
                    MMA_BF16(acc[mi][ni], al, bh[ni]);                                       \
                }                                                                            \
            }                                                                                \
        }                                                                                    \
        __syncthreads();                                                                     \
    }

// ==================== generic HMMA NN projection (bf16 hi/lo out) ====================
__global__ __launch_bounds__(256, 2)
void hmma_nn_kernel(const __nv_bfloat16* __restrict__ Ah, const __nv_bfloat16* __restrict__ Al,
                    const __nv_bfloat16* __restrict__ Bh, const __nv_bfloat16* __restrict__ Bl,
                    const float* __restrict__ bias,
                    __nv_bfloat16* __restrict__ Ch, __nv_bfloat16* __restrict__ Cl,
                    int K, int ldc) {
    extern __shared__ uint32_t smw[];
    const int tid  = threadIdx.x;
    const int lane = tid & 31;
    const int w    = tid >> 5;
    const int wm   = w & 1;
    const int wn   = w >> 1;
    const int r4   = lane >> 2;
    const int tg   = lane & 3;
    const int bm   = blockIdx.y * 128;
    const int bn   = blockIdx.x * 128;
    const int NCHUNK = K / KCH;
    const uint32_t smem0 = smem_u32_of(smw);

    const int lrow = lane & 7, grp = lane >> 3;
    const int a_row_off = ((grp & 1) << 3) + lrow;
    const int a_kh = (grp >> 1) * 4;
    const int b_row_off = ((grp >> 1) << 3) + lrow;
    const int b_kh = (grp & 1) * 4;

    float acc[4][4][4];
#pragma unroll
    for (int i = 0; i < 4; i++)
#pragma unroll
        for (int j = 0; j < 4; j++)
#pragma unroll
            for (int q = 0; q < 4; q++) acc[i][j][q] = 0.f;

    HMMA_MAINLOOP(NCHUNK, Ah, Al, Bh, Bl, K, K)

#pragma unroll
    for (int ni = 0; ni < 4; ni++) {
        int col = bn + wn * 32 + ni * 8 + tg * 2;
        float b0 = bias[col], b1 = bias[col + 1];
#pragma unroll
        for (int mi = 0; mi < 4; mi++) {
            int row0 = bm + wm * 64 + mi * 16 + r4;
            float v00 = acc[mi][ni][0] + b0, v01 = acc[mi][ni][1] + b1;
            float v10 = acc[mi][ni][2] + b0, v11 = acc[mi][ni][3] + b1;
            uint32_t lo0, lo1;
            uint32_t hi0 = pack_hi2(v00, v01, lo0);
            uint32_t hi1 = pack_hi2(v10, v11, lo1);
            size_t o0 = (size_t)row0 * ldc + col;
            size_t o1 = (size_t)(row0 + 8) * ldc + col;
            *(uint32_t*)(Ch + o0) = hi0;
            *(uint32_t*)(Cl + o0) = lo0;
            *(uint32_t*)(Ch + o1) = hi1;
            *(uint32_t*)(Cl + o1) = lo1;
        }
    }
}

// ==================== merged score GEMM (all 4 mats, one launch) ====================
__global__ __launch_bounds__(256, 2)
void score_kernel(const float* __restrict__ IW) {
    extern __shared__ uint32_t smw[];
    const int tid  = threadIdx.x;
    const int lane = tid & 31;
    const int w    = tid >> 5;
    const int wm   = w & 1;
    const int wn   = w >> 1;
    const int r4   = lane >> 2;
    const int tg   = lane & 3;
    const int z    = blockIdx.z;
    const int job  = z >> 5;
    const int b    = z & 31;
    const int tile = blockIdx.x;
    const int NCHUNK = DOUT / KCH;   // 16
    const uint32_t smem0 = smem_u32_of(smw);

    const int lrow = lane & 7, grp = lane >> 3;
    const int a_row_off = ((grp & 1) << 3) + lrow;
    const int a_kh = (grp >> 1) * 4;
    const int b_row_off = ((grp >> 1) << 3) + lrow;
    const int b_kh = (grp & 1) * 4;

    const size_t sQK = (size_t)LENZ * 1536;
    const size_t sCP = (size_t)LCPD * 1024;
    const size_t sIW = (size_t)LCPD * LENZ;

    const __nv_bfloat16 *Ah, *Al, *Bh, *Bl;
    int lda, ldb, M, N, biasMode;
    float* S;
    if (job == 0) {
        Ah = g_QKh; Al = g_QKl; lda = 1536;
        Bh = g_Ch;  Bl = g_Cl;  ldb = 1024;
        M = LENZ; N = LCPD; biasMode = 1; S = g_scratch + OFF_S1;
        Ah += (size_t)b * sQK; Al += (size_t)b * sQK;
        Bh += (size_t)b * sCP; Bl += (size_t)b * sCP;
    } else if (job == 1) {
        Ah = g_Ch + 512; Al = g_Cl + 512; lda = 1024;
        Bh = g_QKh + 512; Bl = g_QKl + 512; ldb = 1536;
        M = LCPD; N = LENZ; biasMode = 2; S = g_scratch + OFF_S2;
        Ah += (size_t)b * sCP; Al += (size_t)b * sCP;
        Bh += (size_t)b * sQK; Bl += (size_t)b * sQK;
    } else if (job == 2) {
        Ah = g_QKh; Al = g_QKl; lda = 1536;
        Bh = g_Ch + CPOFF; Bl = g_Cl + CPOFF; ldb = 1024;
        M = LENZ; N = LCPD; biasMode = 0; S = g_scratch + OFF_S3;
        Ah += (size_t)b * sQK; Al += (size_t)b * sQK;
        Bh += (size_t)b * sCP; Bl += (size_t)b * sCP;
    } else {
        Ah = g_Ch + CPOFF + 512; Al = g_Cl + CPOFF + 512; lda = 1024;
        Bh = g_QKh + 1024; Bl = g_QKl + 1024; ldb = 1536;
        M = LCPD; N = LENZ; biasMode = 0; S = g_scratch + OFF_S4;
        Ah += (size_t)b * sCP; Al += (size_t)b * sCP;
        Bh += (size_t)b * sQK; Bl += (size_t)b * sQK;
    }
    S += (size_t)b * (size_t)M * N;
    const float* bias = IW + (size_t)b * sIW;

    const int bm = (M == LENZ) ? tile * 128 : 0;
    const int bn = (M == LENZ) ? 0 : tile * 128;

    float acc[4][4][4];
#pragma unroll
    for (int i = 0; i < 4; i++)
#pragma unroll
        for (int j = 0; j < 4; j++)
#pragma unroll
            for (int q = 0; q < 4; q++) acc[i][j][q] = 0.f;

    HMMA_MAINLOOP(NCHUNK, Ah, Al, Bh, Bl, lda, ldb)

#pragma unroll
    for (int ni = 0; ni < 4; ni++) {
        int n0 = bn + wn * 32 + ni * 8 + tg * 2;
#pragma unroll
        for (int mi = 0; mi < 4; mi++) {
            int m0 = bm + wm * 64 + mi * 16 + r4;
#pragma unroll
            for (int half = 0; half < 2; half++) {
                int m = m0 + half * 8;
                float v0 = acc[mi][ni][half * 2 + 0] * INV_SCALE;
                float v1 = acc[mi][ni][half * 2 + 1] * INV_SCALE;
                if (biasMode == 1) {
                    v0 += bias[(size_t)n0 * M + m];
                    v1 += bias[(size_t)(n0 + 1) * M + m];
                } else if (biasMode == 2) {
                    v0 += bias[(size_t)m * N + n0];
                    v1 += bias[(size_t)m * N + n0 + 1];
                }
                *(float2*)&S[(size_t)m * N + n0] = make_float2(v0, v1);
            }
        }
    }
}

// ==================== merged softmax + mean -> wbar ====================
template <int LK>
__device__ __forceinline__ void softmax_body(const float* __restrict__ S, float* __restrict__ wbar,
                                             int Lq, int rowsPerBlock, int r0, float* colsum) {
    constexpr int EPL = LK / 32;
    int w = threadIdx.x / 32, lane = threadIdx.x % 32;
    int nw = blockDim.x / 32;

    for (int i = threadIdx.x; i < LK; i += blockDim.x) colsum[i] = 0.f;
    __syncthreads();

    for (int r = r0 + w; r < r0 + rowsPerBlock; r += nw) {
        const float* row = S + (size_t)r * LK;
        float v[EPL];
        float mx = -1e30f;
#pragma unroll
        for (int c = 0; c < EPL / 4; c++) {
            float4 t = *(const float4*)(row + c * 128 + lane * 4);
            v[c * 4 + 0] = t.x; v[c * 4 + 1] = t.y; v[c * 4 + 2] = t.z; v[c * 4 + 3] = t.w;
            mx = fmaxf(mx, fmaxf(fmaxf(t.x, t.y), fmaxf(t.z, t.w)));
        }
#pragma unroll
        for (int o = 16; o > 0; o >>= 1) mx = fmaxf(mx, __shfl_xor_sync(0xffffffffu, mx, o));
        float s = 0.f;
#pragma unroll
        for (int i = 0; i < EPL; i++) { v[i] = __expf(v[i] - mx); s += v[i]; }
#pragma unroll
        for (int o = 16; o > 0; o >>= 1) s += __shfl_xor_sync(0xffffffffu, s, o);
        float inv = 1.f / s;
#pragma unroll
        for (int c = 0; c < EPL / 4; c++)
#pragma unroll
            for (int j = 0; j < 4; j++)
                atomicAdd(&colsum[c * 128 + lane * 4 + j], v[c * 4 + j] * inv);
    }
    __syncthreads();
    float invLq = 1.f / (float)Lq;
    for (int i = threadIdx.x; i < LK; i += blockDim.x)
        atomicAdd(&wbar[i], colsum[i] * invLq);
}

__global__ void softmax_all(void) {
    __shared__ float colsum[512];
    int job = blockIdx.z;
    int b = blockIdx.x;
    int yc = blockIdx.y;
    float* gs = g_scratch;
    if (job == 0) {
        softmax_body<128>(gs + OFF_S1 + (size_t)b * LENZ * LCPD,
                          gs + OFF_WB1 + (size_t)b * LCPD, LENZ, 64, yc * 64, colsum);
    } else if (job == 1) {
        softmax_body<512>(gs + OFF_S2 + (size_t)b * LCPD * LENZ,
                          gs + OFF_WB2 + (size_t)b * LENZ, LCPD, 16, yc * 16, colsum);
    } else if (job == 2) {
        softmax_body<128>(gs + OFF_S3 + (size_t)b * LENZ * LCPD,
                          gs + OFF_WB3 + (size_t)b * LCPD, LENZ, 64, yc * 64, colsum);
    } else {
        softmax_body<512>(gs + OFF_S4 + (size_t)b * LCPD * LENZ,
                          gs + OFF_WB4 + (size_t)b * LENZ, LCPD, 16, yc * 16, colsum);
    }
}

// ==================== weighted feature sums ====================
__global__ void wfeat_small2(const float* __restrict__ subs, const float* __restrict__ prod) {
    int b = blockIdx.x, kc = blockIdx.y, src = blockIdx.z;
    const float* X = src ? prod : subs;
    const float* wbar = g_scratch + (src ? OFF_WB3 : OFF_WB1) + (size_t)b * LCPD;
    float* xb = g_scratch + (src ? OFF_XB3 : OFF_XB1) + (size_t)b * DCPD;
    __shared__ float w[32];
    if (threadIdx.x < 32) w[threadIdx.x] = wbar[kc * 32 + threadIdx.x];
    __syncthreads();
    int d = threadIdx.x;
    float acc = 0.f;
    const float* xp = X + ((size_t)b * LCPD + kc * 32) * DCPD + d;
#pragma unroll 8
    for (int k = 0; k < 32; k++) acc += w[k] * xp[(size_t)k * DCPD];
    atomicAdd(&xb[d], acc);
}

__global__ void wfeat_enz(const float* __restrict__ X) {
    int b = blockIdx.x;
    int d = blockIdx.y * 256 + threadIdx.x;
    const float* w2g = g_scratch + OFF_WB2 + (size_t)b * LENZ;
    const float* w4g = g_scratch + OFF_WB4 + (size_t)b * LENZ;
    __shared__ float s2[LENZ], s4[LENZ];
    for (int i = threadIdx.x; i < LENZ; i += 256) {
        s2[i] = w2g[i];
        s4[i] = w4g[i];
    }
    __syncthreads();
    float a2 = 0.f, a4 = 0.f;
    const float* xp = X + (size_t)b * LENZ * DENZ + d;
#pragma unroll 8
    for (int k = 0; k < LENZ; k++) {
        float x = xp[(size_t)k * DENZ];
        a2 += s2[k] * x;
        a4 += s4[k] * x;
    }
    g_scratch[OFF_XB2 + (size_t)b * DENZ + d] = a2;
    g_scratch[OFF_XB4 + (size_t)b * DENZ + d] = a4;
}

// ==================== final GEMVs ====================
__global__ __launch_bounds__(512) void final_out(
        const float* __restrict__ Wv0, const float* __restrict__ bv0,
        const float* __restrict__ Wv1, const float* __restrict__ bv1,
        const float* __restrict__ Wv2, const float* __restrict__ bv2,
        const float* __restrict__ Wv3, const float* __restrict__ bv3,
        float* __restrict__ out) {
    int b = blockIdx.x, p = blockIdx.y, d = threadIdx.x;
    const float* xb; const float* Wv; const float* bv; int Kd;
    if (p == 0)      { xb = g_scratch + OFF_XB1 + (size_t)b * DCPD; Wv = Wv0; bv = bv0; Kd = DCPD; }
    else if (p == 1) { xb = g_scratch + OFF_XB2 + (size_t)b * DENZ; Wv = Wv1; bv = bv1; Kd = DENZ; }
    else if (p == 2) { xb = g_scratch + OFF_XB3 + (size_t)b * DCPD; Wv = Wv2; bv = bv2; Kd = DCPD; }
    else             { xb = g_scratch + OFF_XB4 + (size_t)b * DENZ; Wv = Wv3; bv = bv3; Kd = DENZ; }

    __shared__ float xs[DENZ];
    for (int i = threadIdx.x; i < Kd; i += 512) xs[i] = xb[i];
    __syncthreads();

    float acc = bv[d];
#pragma unroll 4
    for (int j = 0; j < Kd; j++) acc += xs[j] * Wv[(size_t)j * DOUT + d];
    out[(size_t)b * 2048 + p * 512 + d] = acc;
}

// ==================== launch ====================
extern "C" void kernel_launch(void* const* d_in, const int* in_sizes, int n_in,
                              void* d_out, int out_size) {
    const float* enz   = (const float*)d_in[0];
    const float* subs  = (const float*)d_in[1];
    const float* prod  = (const float*)d_in[2];
    const float* IW    = (const float*)d_in[6];
    const float* enz_Wq = (const float*)d_in[7];
    const float* enz_bq = (const float*)d_in[8];
    const float* enz_Wk = (const float*)d_in[9];
    const float* enz_bk = (const float*)d_in[10];
    const float* enz_Wv = (const float*)d_in[11];
    const float* enz_bv = (const float*)d_in[12];
    const float* sub_Wq = (const float*)d_in[13];
    const float* sub_bq = (const float*)d_in[14];
    const float* sub_Wk = (const float*)d_in[15];
    const float* sub_bk = (const float*)d_in[16];
    const float* sub_Wv = (const float*)d_in[17];
    const float* sub_bv = (const float*)d_in[18];
    const float* prod_Wq = (const float*)d_in[19];
    const float* prod_bq = (const float*)d_in[20];
    const float* prod_Wk = (const float*)d_in[21];
    const float* prod_bk = (const float*)d_in[22];
    const float* prod_Wv = (const float*)d_in[23];
    const float* prod_bv = (const float*)d_in[24];
    float* out = (float*)d_out;

    static float* gs = nullptr;
    static __nv_bfloat16 *Ah = nullptr, *Al = nullptr, *Wht = nullptr, *Wlt = nullptr;
    static __nv_bfloat16 *X2h = nullptr, *X2l = nullptr, *W2h = nullptr, *W2l = nullptr;
    static __nv_bfloat16 *QKh = nullptr, *QKl = nullptr, *Ch = nullptr, *Cl = nullptr;
    static bool inited = false;
    if (!inited) {
        void* p = nullptr;
        cudaGetSymbolAddress(&p, g_scratch);  gs = (float*)p;
        cudaGetSymbolAddress(&p, g_Ah);       Ah = (__nv_bfloat16*)p;
        cudaGetSymbolAddress(&p, g_Al);       Al = (__nv_bfloat16*)p;
        cudaGetSymbolAddress(&p, g_Wht);      Wht = (__nv_bfloat16*)p;
        cudaGetSymbolAddress(&p, g_Wlt);      Wlt = (__nv_bfloat16*)p;
        cudaGetSymbolAddress(&p, g_X2h);      X2h = (__nv_bfloat16*)p;
        cudaGetSymbolAddress(&p, g_X2l);      X2l = (__nv_bfloat16*)p;
        cudaGetSymbolAddress(&p, g_W2h);      W2h = (__nv_bfloat16*)p;
        cudaGetSymbolAddress(&p, g_W2l);      W2l = (__nv_bfloat16*)p;
        cudaGetSymbolAddress(&p, g_QKh);      QKh = (__nv_bfloat16*)p;
        cudaGetSymbolAddress(&p, g_QKl);      QKl = (__nv_bfloat16*)p;
        cudaGetSymbolAddress(&p, g_Ch);       Ch = (__nv_bfloat16*)p;
        cudaGetSymbolAddress(&p, g_Cl);       Cl = (__nv_bfloat16*)p;
        cudaFuncSetAttribute(hmma_nn_kernel,
                             cudaFuncAttributeMaxDynamicSharedMemorySize, SMEM_MMA_BYTES);
        cudaFuncSetAttribute(score_kernel,
                             cudaFuncAttributeMaxDynamicSharedMemorySize, SMEM_MMA_BYTES);
        inited = true;
    }

    // #1: merged head (all conversions + biases + zeroing)
    head_kernel<<<HB9, 256>>>(enz, subs, prod,
                              enz_Wq, enz_bq, enz_Wk, enz_bk,
                              sub_Wq, sub_bq, sub_Wk, sub_bk,
                              prod_Wq, prod_bq, prod_Wk, prod_bk);

    // #2, #3: cpd projections on HMMA
    hmma_nn_kernel<<<dim3(1024 / 128, (NB * LCPD) / 128), 256, SMEM_MMA_BYTES>>>(
        X2h, X2l, W2h, W2l, gs + OFF_BCS, Ch, Cl, DCPD, 1024);
    hmma_nn_kernel<<<dim3(1024 / 128, (NB * LCPD) / 128), 256, SMEM_MMA_BYTES>>>(
        X2h + N_CPD, X2l + N_CPD, W2h + N_W2, W2l + N_W2,
        gs + OFF_BCP, Ch + CPOFF, Cl + CPOFF, DCPD, 1024);

    // #4: BIG projection (positioned 4th for ncu capture)
    hmma_nn_kernel<<<dim3(1536 / 128, (NB * LENZ) / 128), 256, SMEM_MMA_BYTES>>>(
        Ah, Al, Wht, Wlt, gs + OFF_BCE, QKh, QKl, DENZ, 1536);

    // #5: all four score GEMMs
    score_kernel<<<dim3(4, 1, 128), 256, SMEM_MMA_BYTES>>>(IW);

    // #6: all four softmax+mean reductions
    softmax_all<<<dim3(NB, 8, 4), 256>>>();

    // #7, #8: weighted feature sums
    wfeat_small2<<<dim3(NB, 4, 2), 256>>>(subs, prod);
    wfeat_enz<<<dim3(NB, DENZ / 256), 256>>>(enz);

    // #9: final GEMVs
    final_out<<<dim3(NB, 4), 512>>>(enz_Wv, enz_bv,
                                    sub_Wv, sub_bv,
                                    enz_Wv, enz_bv,
                                    prod_Wv, prod_bv,
                                    out);
}

// round 17
// speedup vs baseline: 1.1406x; 1.0053x over previous
#include <cuda_runtime.h>
#include <cuda_bf16.h>
#include <math.h>
#include <stdint.h>

// Problem dims
#define NB    32
#define LENZ  512
#define LCPD  128
#define DENZ  1280
#define DCPD  256
#define DOUT  512

static constexpr float INV_SCALE = 0.04419417382415922f; // 1/sqrt(512)

// ==================== scratch (fp32) ====================
static constexpr size_t SZ_S_BIG = (size_t)NB * LENZ * LCPD;
static constexpr size_t SZ_BCE   = 1536;
static constexpr size_t SZ_BCS   = 1024;
static constexpr size_t SZ_BCP   = 1024;
static constexpr size_t SZ_WB1   = (size_t)NB * LCPD;
static constexpr size_t SZ_WB2   = (size_t)NB * LENZ;
static constexpr size_t SZ_WB3   = (size_t)NB * LCPD;
static constexpr size_t SZ_WB4   = (size_t)NB * LENZ;
static constexpr size_t SZ_XB1   = (size_t)NB * DCPD;
static constexpr size_t SZ_XB3   = (size_t)NB * DCPD;
static constexpr size_t SZ_XB2   = (size_t)NB * DENZ;
static constexpr size_t SZ_XB4   = (size_t)NB * DENZ;

static constexpr size_t OFF_S1    = 0;
static constexpr size_t OFF_S2    = OFF_S1 + SZ_S_BIG;
static constexpr size_t OFF_S3    = OFF_S2 + SZ_S_BIG;
static constexpr size_t OFF_S4    = OFF_S3 + SZ_S_BIG;
static constexpr size_t OFF_BCE   = OFF_S4 + SZ_S_BIG;
static constexpr size_t OFF_BCS   = OFF_BCE + SZ_BCE;
static constexpr size_t OFF_BCP   = OFF_BCS + SZ_BCS;
static constexpr size_t OFF_WB1   = OFF_BCP + SZ_BCP;
static constexpr size_t OFF_WB2   = OFF_WB1 + SZ_WB1;
static constexpr size_t OFF_WB3   = OFF_WB2 + SZ_WB2;
static constexpr size_t OFF_WB4   = OFF_WB3 + SZ_WB3;
static constexpr size_t OFF_XB1   = OFF_WB4 + SZ_WB4;
static constexpr size_t OFF_XB3   = OFF_XB1 + SZ_XB1;
static constexpr size_t OFF_XB2   = OFF_XB3 + SZ_XB3;
static constexpr size_t OFF_XB4   = OFF_XB2 + SZ_XB2;
static constexpr size_t SCRATCH_TOTAL = OFF_XB4 + SZ_XB4;
static constexpr size_t ZERO_LEN = SZ_WB1 + SZ_WB2 + SZ_WB3 + SZ_WB4 + SZ_XB1 + SZ_XB3; // 57344
static_assert(OFF_XB1 == OFF_WB1 + SZ_WB1 + SZ_WB2 + SZ_WB3 + SZ_WB4, "zero region contiguity");
static_assert(OFF_XB3 == OFF_XB1 + SZ_XB1, "zero region contiguity");

static __device__ float g_scratch[SCRATCH_TOTAL];

// bf16 hi/lo operands
static __device__ __align__(16) __nv_bfloat16 g_Ah[(size_t)NB * LENZ * DENZ];
static __device__ __align__(16) __nv_bfloat16 g_Al[(size_t)NB * LENZ * DENZ];
static __device__ __align__(16) __nv_bfloat16 g_Wht[(size_t)1536 * DENZ];   // [1536,1280]
static __device__ __align__(16) __nv_bfloat16 g_Wlt[(size_t)1536 * DENZ];
static __device__ __align__(16) __nv_bfloat16 g_X2h[(size_t)2 * NB * LCPD * DCPD]; // subs|prod
static __device__ __align__(16) __nv_bfloat16 g_X2l[(size_t)2 * NB * LCPD * DCPD];
static __device__ __align__(16) __nv_bfloat16 g_W2h[(size_t)2 * 1024 * DCPD];      // [1024,256] x2
static __device__ __align__(16) __nv_bfloat16 g_W2l[(size_t)2 * 1024 * DCPD];
// projection outputs as bf16 hi/lo
static __device__ __align__(16) __nv_bfloat16 g_QKh[(size_t)NB * LENZ * 1536];
static __device__ __align__(16) __nv_bfloat16 g_QKl[(size_t)NB * LENZ * 1536];
static __device__ __align__(16) __nv_bfloat16 g_Ch[(size_t)2 * NB * LCPD * 1024];  // sub|prod
static __device__ __align__(16) __nv_bfloat16 g_Cl[(size_t)2 * NB * LCPD * 1024];

static constexpr size_t CPOFF = (size_t)NB * LCPD * 1024;  // prod offset in g_Ch/g_Cl

// ==================== merged head kernel ====================
static constexpr size_t N_ENZ  = (size_t)NB * LENZ * DENZ;
static constexpr size_t N_W    = (size_t)1536 * DENZ;
static constexpr size_t N_CPD  = (size_t)NB * LCPD * DCPD;
static constexpr size_t N_W2   = (size_t)1024 * DCPD;

static constexpr int HB0 = (int)(N_ENZ / 1024);
static constexpr int HB1 = HB0 + (int)(N_W / 1024);
static constexpr int HB2 = HB1 + (int)(N_CPD / 1024);
static constexpr int HB3 = HB2 + (int)(N_CPD / 1024);
static constexpr int HB4 = HB3 + (int)(N_W2 / 1024);
static constexpr int HB5 = HB4 + (int)(N_W2 / 1024);
static constexpr int HB6 = HB5 + 6;
static constexpr int HB7 = HB6 + 4;
static constexpr int HB8 = HB7 + 4;
static constexpr int HB9 = HB8 + (int)(ZERO_LEN / 1024);
static_assert((size_t)HB0 * 1024 == N_ENZ, "convA range");
static_assert((size_t)(HB1 - HB0) * 1024 == N_W, "convW range");
static_assert((size_t)(HB3 - HB2) * 1024 == N_CPD, "convX range");
static_assert((size_t)(HB5 - HB4) * 1024 == N_W2, "convW2 range");
static_assert((size_t)(HB9 - HB8) * 1024 == ZERO_LEN, "zero range");

__device__ __forceinline__ void split4_store(const float* xs, __nv_bfloat16* H,
                                             __nv_bfloat16* L, size_t i) {
    unsigned short hs[4], ls[4];
#pragma unroll
    for (int j = 0; j < 4; j++) {
        __nv_bfloat16 h = __float2bfloat16(xs[j]);
        hs[j] = __bfloat16_as_ushort(h);
        ls[j] = __bfloat16_as_ushort(__float2bfloat16(xs[j] - __bfloat162float(h)));
    }
    *(uint2*)(H + i) = make_uint2((uint32_t)hs[0] | ((uint32_t)hs[1] << 16),
                                  (uint32_t)hs[2] | ((uint32_t)hs[3] << 16));
    *(uint2*)(L + i) = make_uint2((uint32_t)ls[0] | ((uint32_t)ls[1] << 16),
                                  (uint32_t)ls[2] | ((uint32_t)ls[3] << 16));
}

__global__ void head_kernel(const float* __restrict__ enz,
                            const float* __restrict__ subs,
                            const float* __restrict__ prod,
                            const float* __restrict__ enz_Wq, const float* __restrict__ enz_bq,
                            const float* __restrict__ enz_Wk, const float* __restrict__ enz_bk,
                            const float* __restrict__ sub_Wq, const float* __restrict__ sub_bq,
                            const float* __restrict__ sub_Wk, const float* __restrict__ sub_bk,
                            const float* __restrict__ prod_Wq, const float* __restrict__ prod_bq,
                            const float* __restrict__ prod_Wk, const float* __restrict__ prod_bk) {
    const int blk = blockIdx.x;
    const int tid = threadIdx.x;

    if (blk < HB0) {
        size_t i = ((size_t)blk * 256 + tid) * 4;
        float4 v = *(const float4*)(enz + i);
        float xs[4] = {v.x, v.y, v.z, v.w};
        split4_store(xs, g_Ah, g_Al, i);
    } else if (blk < HB1) {
        size_t flat = ((size_t)(blk - HB0) * 256 + tid) * 4;
        int n = (int)(flat / DENZ), k = (int)(flat % DENZ);
        const float* src; int nn = n;
        if (n < 512)       src = enz_Wq;
        else if (n < 1024) { src = sub_Wk;  nn = n - 512; }
        else               { src = prod_Wk; nn = n - 1024; }
        float xs[4];
#pragma unroll
        for (int j = 0; j < 4; j++) xs[j] = src[(size_t)(k + j) * 512 + nn];
        split4_store(xs, g_Wht, g_Wlt, flat);
    } else if (blk < HB2) {
        size_t i = ((size_t)(blk - HB1) * 256 + tid) * 4;
        float4 v = *(const float4*)(subs + i);
        float xs[4] = {v.x, v.y, v.z, v.w};
        split4_store(xs, g_X2h, g_X2l, i);
    } else if (blk < HB3) {
        size_t i = ((size_t)(blk - HB2) * 256 + tid) * 4;
        float4 v = *(const float4*)(prod + i);
        float xs[4] = {v.x, v.y, v.z, v.w};
        split4_store(xs, g_X2h + N_CPD, g_X2l + N_CPD, i);
    } else if (blk < HB4) {
        size_t flat = ((size_t)(blk - HB3) * 256 + tid) * 4;
        int n = (int)(flat / DCPD), k = (int)(flat % DCPD);
        const float* src = (n < 512) ? enz_Wk : sub_Wq;
        int nn = (n < 512) ? n : n - 512;
        float xs[4];
#pragma unroll
        for (int j = 0; j < 4; j++) xs[j] = src[(size_t)(k + j) * 512 + nn];
        split4_store(xs, g_W2h, g_W2l, flat);
    } else if (blk < HB5) {
        size_t flat = ((size_t)(blk - HB4) * 256 + tid) * 4;
        int n = (int)(flat / DCPD), k = (int)(flat % DCPD);
        const float* src = (n < 512) ? enz_Wk : prod_Wq;
        int nn = (n < 512) ? n : n - 512;
        float xs[4];
#pragma unroll
        for (int j = 0; j < 4; j++) xs[j] = src[(size_t)(k + j) * 512 + nn];
        split4_store(xs, g_W2h + N_W2, g_W2l + N_W2, flat);
    } else if (blk < HB6) {
        int c = (blk - HB5) * 256 + tid;
        if (c < 1536) {
            float v;
            if (c < 512)       v = enz_bq[c];
            else if (c < 1024) v = sub_bk[c - 512];
            else               v = prod_bk[c - 1024];
            g_scratch[OFF_BCE + c] = v;
        }
    } else if (blk < HB7) {
        int c = (blk - HB6) * 256 + tid;
        if (c < 1024)
            g_scratch[OFF_BCS + c] = (c < 512) ? enz_bk[c] : sub_bq[c - 512];
    } else if (blk < HB8) {
        int c = (blk - HB7) * 256 + tid;
        if (c < 1024)
            g_scratch[OFF_BCP + c] = (c < 512) ? enz_bk[c] : prod_bq[c - 512];
    } else if (blk < HB9) {
        size_t i = ((size_t)(blk - HB8) * 256 + tid) * 4;
        if (i < ZERO_LEN)
            *(float4*)&g_scratch[OFF_WB1 + i] = make_float4(0.f, 0.f, 0.f, 0.f);
    }
}

// ==================== HMMA helpers ====================
#define MMA_BF16(d, a, b) \
    asm volatile("mma.sync.aligned.m16n8k16.row.col.f32.bf16.bf16.f32 " \
                 "{%0,%1,%2,%3}, {%4,%5,%6,%7}, {%8,%9}, {%0,%1,%2,%3};" \
                 : "+f"((d)[0]), "+f"((d)[1]), "+f"((d)[2]), "+f"((d)[3]) \
                 : "r"((a)[0]), "r"((a)[1]), "r"((a)[2]), "r"((a)[3]), \
                   "r"((b)[0]), "r"((b)[1]))

#define LDSM_X4(r0, r1, r2, r3, addr) \
    asm volatile("ldmatrix.sync.aligned.m8n8.x4.shared.b16 {%0,%1,%2,%3}, [%4];" \
                 : "=r"(r0), "=r"(r1), "=r"(r2), "=r"(r3) : "r"(addr))

// cp.async: L2 -> smem, 16B, bypasses L1 and the register file (sm_80+ baseline PTX)
#define CP_ASYNC16(smem_u32, gptr) \
    asm volatile("cp.async.cg.shared.global [%0], [%1], 16;" \
                 :: "r"(smem_u32), "l"(gptr) : "memory")
#define CP_COMMIT() asm volatile("cp.async.commit_group;" ::: "memory")
#define CP_WAIT0()  asm volatile("cp.async.wait_group 0;" ::: "memory")

__device__ __forceinline__ uint32_t smem_u32_of(const void* p) {
    uint32_t a;
    asm("{ .reg .u64 t; cvta.to.shared.u64 t, %1; cvt.u32.u64 %0, t; }" : "=r"(a) : "l"(p));
    return a;
}

__device__ __forceinline__ uint32_t pack_hi2(float v0, float v1, uint32_t& lo_out) {
    __nv_bfloat16 h0 = __float2bfloat16(v0);
    __nv_bfloat16 h1 = __float2bfloat16(v1);
    __nv_bfloat16 l0 = __float2bfloat16(v0 - __bfloat162float(h0));
    __nv_bfloat16 l1 = __float2bfloat16(v1 - __bfloat162float(h1));
    lo_out = (uint32_t)__bfloat16_as_ushort(l0) | ((uint32_t)__bfloat16_as_ushort(l1) << 16);
    return (uint32_t)__bfloat16_as_ushort(h0) | ((uint32_t)__bfloat16_as_ushort(h1) << 16);
}

static constexpr int KCH = 32;
static constexpr int ROW_W = 20;                // 16 data words + 4 pad (80B rows, 16B-aligned)
static constexpr int TILE_W = 128 * ROW_W;      // 2560 words (10KB)
static constexpr int STAGE_W = 4 * TILE_W;      // 40KB
static constexpr int NSTAGE = 2;                // 2 stages -> 80KB/CTA, 2 CTAs resident
static constexpr int SMEM_MMA_BYTES = NSTAGE * STAGE_W * 4;  // 81920
static_assert((ROW_W * 4) % 16 == 0, "row stride must be 16B-aligned for cp.async");

// Fill one stage: each thread issues 8 cp.async of 16B.
__device__ __forceinline__ void fill_stage(uint32_t st_base, int tid,
                                           const __nv_bfloat16* Ah, const __nv_bfloat16* Al,
                                           const __nv_bfloat16* Bh, const __nv_bfloat16* Bl,
                                           int bm, int bn, int lda, int ldb, int k0) {
#pragma unroll
    for (int i = 0; i < 2; i++) {
        int u = tid + i * 256;
        int r = u >> 2, c16 = u & 3;
        uint32_t so = st_base + (uint32_t)(r * ROW_W + c16 * 4) * 4;
        size_t ga = (size_t)(bm + r) * lda + k0 + c16 * 8;
        size_t gb = (size_t)(bn + r) * ldb + k0 + c16 * 8;
        CP_ASYNC16(so + 0 * TILE_W * 4, Ah + ga);
        CP_ASYNC16(so + 1 * TILE_W * 4, Al + ga);
        CP_ASYNC16(so + 2 * TILE_W * 4, Bh + gb);
        CP_ASYNC16(so + 3 * TILE_W * 4, Bl + gb);
    }
}

// 2-stage mainloop, ONE barrier per chunk (the top-of-loop barrier also proves
// all warps finished the previous chunk's reads, so refilling is safe).
// MMA ordering: product-major over ni -> dependency distance 4 on each acc.
// Per-element accumulation order unchanged (hh, hl, lh) -> bit-identical.
#define HMMA_MAINLOOP(NCHUNK_, Ah_, Al_, Bh_, Bl_, lda_, ldb_)                               \
    fill_stage(smem0, tid, Ah_, Al_, Bh_, Bl_, bm, bn, lda_, ldb_, 0);                       \
    CP_COMMIT();                                                                             \
    for (int ch = 0; ch < (NCHUNK_); ch++) {                                                 \
        CP_WAIT0();                                                                          \
        __syncthreads();                                                                     \
        if (ch + 1 < (NCHUNK_)) {                                                            \
            fill_stage(smem0 + (((ch & 1) ^ 1) * STAGE_W) * 4, tid, Ah_, Al_, Bh_, Bl_,      \
                       bm, bn, lda_, ldb_, (ch + 1) * KCH);                                  \
            CP_COMMIT();                                                                     \
        }                                                                                    \
        const uint32_t stAh = smem0 + ((ch & 1) * STAGE_W) * 4;                              \
        const uint32_t stAl = stAh + TILE_W * 4;                                             \
        const uint32_t stBh = stAh + 2 * TILE_W * 4;                                         \
        const uint32_t stBl = stAh + 3 * TILE_W * 4;                                         \
        _Pragma("unroll")                                                                    \
        for (int ks = 0; ks < 2; ks++) {                                                     \
            const int kw = ks * 8;                                                           \
            uint32_t bh[4][2], bl[4][2];                                                     \
            _Pragma("unroll")                                                                \
            for (int p = 0; p < 2; p++) {                                                    \
                uint32_t wo = (uint32_t)((wn * 32 + p * 16 + b_row_off) * ROW_W              \
                                         + kw + b_kh) * 4;                                   \
                uint32_t t0, t1, t2, t3;                                                     \
                LDSM_X4(t0, t1, t2, t3, stBh + wo);                                          \
                bh[2 * p][0] = t0; bh[2 * p][1] = t1;                                        \
                bh[2 * p + 1][0] = t2; bh[2 * p + 1][1] = t3;                                \
                LDSM_X4(t0, t1, t2, t3, stBl + wo);                                          \
                bl[2 * p][0] = t0; bl[2 * p][1] = t1;                                        \
                bl[2 * p + 1][0] = t2; bl[2 * p + 1][1] = t3;                                \
            }                                                                                \
            _Pragma("unroll")                                                                \
            for (int mi = 0; mi < 4; mi++) {                                                 \
                uint32_t ah[4], al[4];                                                       \
                uint32_t wo = (uint32_t)((wm * 64 + mi * 16 + a_row_off) * ROW_W             \
                                         + kw + a_kh) * 4;                                   \
                LDSM_X4(ah[0], ah[1], ah[2], ah[3], stAh + wo);                              \
                LDSM_X4(al[0], al[1], al[2], al[3], stAl + wo);                              \
                _Pragma("unroll")                                                            \
                for (int ni = 0; ni < 4; ni++) MMA_BF16(acc[mi][ni], ah, bh[ni]);            \
                _Pragma("unroll")                                                            \
                for (int ni = 0; ni < 4; ni++) MMA_BF16(acc[mi][ni], ah, bl[ni]);            \
                _Pragma("unroll")                                                            \
                for (int ni = 0; ni < 4; ni++) MMA_BF16(acc[mi][ni], al, bh[ni]);            \
            }                                                                                \
        }                                                                                    \
    }

// ==================== generic HMMA NN projection (bf16 hi/lo out) ====================
__global__ __launch_bounds__(256, 2)
void hmma_nn_kernel(const __nv_bfloat16* __restrict__ Ah, const __nv_bfloat16* __restrict__ Al,
                    const __nv_bfloat16* __restrict__ Bh, const __nv_bfloat16* __restrict__ Bl,
                    const float* __restrict__ bias,
                    __nv_bfloat16* __restrict__ Ch, __nv_bfloat16* __restrict__ Cl,
                    int K, int ldc) {
    extern __shared__ uint32_t smw[];
    const int tid  = threadIdx.x;
    const int lane = tid & 31;
    const int w    = tid >> 5;
    const int wm   = w & 1;
    const int wn   = w >> 1;
    const int r4   = lane >> 2;
    const int tg   = lane & 3;
    const int bm   = blockIdx.y * 128;
    const int bn   = blockIdx.x * 128;
    const int NCHUNK = K / KCH;
    const uint32_t smem0 = smem_u32_of(smw);

    const int lrow = lane & 7, grp = lane >> 3;
    const int a_row_off = ((grp & 1) << 3) + lrow;
    const int a_kh = (grp >> 1) * 4;
    const int b_row_off = ((grp >> 1) << 3) + lrow;
    const int b_kh = (grp & 1) * 4;

    float acc[4][4][4];
#pragma unroll
    for (int i = 0; i < 4; i++)
#pragma unroll
        for (int j = 0; j < 4; j++)
#pragma unroll
            for (int q = 0; q < 4; q++) acc[i][j][q] = 0.f;

    HMMA_MAINLOOP(NCHUNK, Ah, Al, Bh, Bl, K, K)

#pragma unroll
    for (int ni = 0; ni < 4; ni++) {
        int col = bn + wn * 32 + ni * 8 + tg * 2;
        float b0 = bias[col], b1 = bias[col + 1];
#pragma unroll
        for (int mi = 0; mi < 4; mi++) {
            int row0 = bm + wm * 64 + mi * 16 + r4;
            float v00 = acc[mi][ni][0] + b0, v01 = acc[mi][ni][1] + b1;
            float v10 = acc[mi][ni][2] + b0, v11 = acc[mi][ni][3] + b1;
            uint32_t lo0, lo1;
            uint32_t hi0 = pack_hi2(v00, v01, lo0);
            uint32_t hi1 = pack_hi2(v10, v11, lo1);
            size_t o0 = (size_t)row0 * ldc + col;
            size_t o1 = (size_t)(row0 + 8) * ldc + col;
            *(uint32_t*)(Ch + o0) = hi0;
            *(uint32_t*)(Cl + o0) = lo0;
            *(uint32_t*)(Ch + o1) = hi1;
            *(uint32_t*)(Cl + o1) = lo1;
        }
    }
}

// ==================== merged score GEMM (all 4 mats, one launch) ====================
__global__ __launch_bounds__(256, 2)
void score_kernel(const float* __restrict__ IW) {
    extern __shared__ uint32_t smw[];
    const int tid  = threadIdx.x;
    const int lane = tid & 31;
    const int w    = tid >> 5;
    const int wm   = w & 1;
    const int wn   = w >> 1;
    const int r4   = lane >> 2;
    const int tg   = lane & 3;
    const int z    = blockIdx.z;
    const int job  = z >> 5;
    const int b    = z & 31;
    const int tile = blockIdx.x;
    const int NCHUNK = DOUT / KCH;   // 16
    const uint32_t smem0 = smem_u32_of(smw);

    const int lrow = lane & 7, grp = lane >> 3;
    const int a_row_off = ((grp & 1) << 3) + lrow;
    const int a_kh = (grp >> 1) * 4;
    const int b_row_off = ((grp >> 1) << 3) + lrow;
    const int b_kh = (grp & 1) * 4;

    const size_t sQK = (size_t)LENZ * 1536;
    const size_t sCP = (size_t)LCPD * 1024;
    const size_t sIW = (size_t)LCPD * LENZ;

    const __nv_bfloat16 *Ah, *Al, *Bh, *Bl;
    int lda, ldb, M, N, biasMode;
    float* S;
    if (job == 0) {
        Ah = g_QKh; Al = g_QKl; lda = 1536;
        Bh = g_Ch;  Bl = g_Cl;  ldb = 1024;
        M = LENZ; N = LCPD; biasMode = 1; S = g_scratch + OFF_S1;
        Ah += (size_t)b * sQK; Al += (size_t)b * sQK;
        Bh += (size_t)b * sCP; Bl += (size_t)b * sCP;
    } else if (job == 1) {
        Ah = g_Ch + 512; Al = g_Cl + 512; lda = 1024;
        Bh = g_QKh + 512; Bl = g_QKl + 512; ldb = 1536;
        M = LCPD; N = LENZ; biasMode = 2; S = g_scratch + OFF_S2;
        Ah += (size_t)b * sCP; Al += (size_t)b * sCP;
        Bh += (size_t)b * sQK; Bl += (size_t)b * sQK;
    } else if (job == 2) {
        Ah = g_QKh; Al = g_QKl; lda = 1536;
        Bh = g_Ch + CPOFF; Bl = g_Cl + CPOFF; ldb = 1024;
        M = LENZ; N = LCPD; biasMode = 0; S = g_scratch + OFF_S3;
        Ah += (size_t)b * sQK; Al += (size_t)b * sQK;
        Bh += (size_t)b * sCP; Bl += (size_t)b * sCP;
    } else {
        Ah = g_Ch + CPOFF + 512; Al = g_Cl + CPOFF + 512; lda = 1024;
        Bh = g_QKh + 1024; Bl = g_QKl + 1024; ldb = 1536;
        M = LCPD; N = LENZ; biasMode = 0; S = g_scratch + OFF_S4;
        Ah += (size_t)b * sCP; Al += (size_t)b * sCP;
        Bh += (size_t)b * sQK; Bl += (size_t)b * sQK;
    }
    S += (size_t)b * (size_t)M * N;
    const float* bias = IW + (size_t)b * sIW;

    const int bm = (M == LENZ) ? tile * 128 : 0;
    const int bn = (M == LENZ) ? 0 : tile * 128;

    float acc[4][4][4];
#pragma unroll
    for (int i = 0; i < 4; i++)
#pragma unroll
        for (int j = 0; j < 4; j++)
#pragma unroll
            for (int q = 0; q < 4; q++) acc[i][j][q] = 0.f;

    HMMA_MAINLOOP(NCHUNK, Ah, Al, Bh, Bl, lda, ldb)

#pragma unroll
    for (int ni = 0; ni < 4; ni++) {
        int n0 = bn + wn * 32 + ni * 8 + tg * 2;
#pragma unroll
        for (int mi = 0; mi < 4; mi++) {
            int m0 = bm + wm * 64 + mi * 16 + r4;
#pragma unroll
            for (int half = 0; half < 2; half++) {
                int m = m0 + half * 8;
                float v0 = acc[mi][ni][half * 2 + 0] * INV_SCALE;
                float v1 = acc[mi][ni][half * 2 + 1] * INV_SCALE;
                if (biasMode == 1) {
                    v0 += bias[(size_t)n0 * M + m];
                    v1 += bias[(size_t)(n0 + 1) * M + m];
                } else if (biasMode == 2) {
                    v0 += bias[(size_t)m * N + n0];
                    v1 += bias[(size_t)m * N + n0 + 1];
                }
                *(float2*)&S[(size_t)m * N + n0] = make_float2(v0, v1);
            }
        }
    }
}

// ==================== merged softmax + mean -> wbar ====================
template <int LK>
__device__ __forceinline__ void softmax_body(const float* __restrict__ S, float* __restrict__ wbar,
                                             int Lq, int rowsPerBlock, int r0, float* colsum) {
    constexpr int EPL = LK / 32;
    int w = threadIdx.x / 32, lane = threadIdx.x % 32;
    int nw = blockDim.x / 32;

    for (int i = threadIdx.x; i < LK; i += blockDim.x) colsum[i] = 0.f;
    __syncthreads();

    for (int r = r0 + w; r < r0 + rowsPerBlock; r += nw) {
        const float* row = S + (size_t)r * LK;
        float v[EPL];
        float mx = -1e30f;
#pragma unroll
        for (int c = 0; c < EPL / 4; c++) {
            float4 t = *(const float4*)(row + c * 128 + lane * 4);
            v[c * 4 + 0] = t.x; v[c * 4 + 1] = t.y; v[c * 4 + 2] = t.z; v[c * 4 + 3] = t.w;
            mx = fmaxf(mx, fmaxf(fmaxf(t.x, t.y), fmaxf(t.z, t.w)));
        }
#pragma unroll
        for (int o = 16; o > 0; o >>= 1) mx = fmaxf(mx, __shfl_xor_sync(0xffffffffu, mx, o));
        float s = 0.f;
#pragma unroll
        for (int i = 0; i < EPL; i++) { v[i] = __expf(v[i] - mx); s += v[i]; }
#pragma unroll
        for (int o = 16; o > 0; o >>= 1) s += __shfl_xor_sync(0xffffffffu, s, o);
        float inv = 1.f / s;
#pragma unroll
        for (int c = 0; c < EPL / 4; c++)
#pragma unroll
            for (int j = 0; j < 4; j++)
                atomicAdd(&colsum[c * 128 + lane * 4 + j], v[c * 4 + j] * inv);
    }
    __syncthreads();
    float invLq = 1.f / (float)Lq;
    for (int i = threadIdx.x; i < LK; i += blockDim.x)
        atomicAdd(&wbar[i], colsum[i] * invLq);
}

__global__ void softmax_all(void) {
    __shared__ float colsum[512];
    int job = blockIdx.z;
    int b = blockIdx.x;
    int yc = blockIdx.y;
    float* gs = g_scratch;
    if (job == 0) {
        softmax_body<128>(gs + OFF_S1 + (size_t)b * LENZ * LCPD,
                          gs + OFF_WB1 + (size_t)b * LCPD, LENZ, 64, yc * 64, colsum);
    } else if (job == 1) {
        softmax_body<512>(gs + OFF_S2 + (size_t)b * LCPD * LENZ,
                          gs + OFF_WB2 + (size_t)b * LENZ, LCPD, 16, yc * 16, colsum);
    } else if (job == 2) {
        softmax_body<128>(gs + OFF_S3 + (size_t)b * LENZ * LCPD,
                          gs + OFF_WB3 + (size_t)b * LCPD, LENZ, 64, yc * 64, colsum);
    } else {
        softmax_body<512>(gs + OFF_S4 + (size_t)b * LCPD * LENZ,
                          gs + OFF_WB4 + (size_t)b * LENZ, LCPD, 16, yc * 16, colsum);
    }
}

// ==================== weighted feature sums ====================
__global__ void wfeat_small2(const float* __restrict__ subs, const float* __restrict__ prod) {
    int b = blockIdx.x, kc = blockIdx.y, src = blockIdx.z;
    const float* X = src ? prod : subs;
    const float* wbar = g_scratch + (src ? OFF_WB3 : OFF_WB1) + (size_t)b * LCPD;
    float* xb = g_scratch + (src ? OFF_XB3 : OFF_XB1) + (size_t)b * DCPD;
    __shared__ float w[32];
    if (threadIdx.x < 32) w[threadIdx.x] = wbar[kc * 32 + threadIdx.x];
    __syncthreads();
    int d = threadIdx.x;
    float acc = 0.f;
    const float* xp = X + ((size_t)b * LCPD + kc * 32) * DCPD + d;
#pragma unroll 8
    for (int k = 0; k < 32; k++) acc += w[k] * xp[(size_t)k * DCPD];
    atomicAdd(&xb[d], acc);
}

__global__ void wfeat_enz(const float* __restrict__ X) {
    int b = blockIdx.x;
    int d = blockIdx.y * 256 + threadIdx.x;
    const float* w2g = g_scratch + OFF_WB2 + (size_t)b * LENZ;
    const float* w4g = g_scratch + OFF_WB4 + (size_t)b * LENZ;
    __shared__ float s2[LENZ], s4[LENZ];
    for (int i = threadIdx.x; i < LENZ; i += 256) {
        s2[i] = w2g[i];
        s4[i] = w4g[i];
    }
    __syncthreads();
    float a2 = 0.f, a4 = 0.f;
    const float* xp = X + (size_t)b * LENZ * DENZ + d;
#pragma unroll 8
    for (int k = 0; k < LENZ; k++) {
        float x = xp[(size_t)k * DENZ];
        a2 += s2[k] * x;
        a4 += s4[k] * x;
    }
    g_scratch[OFF_XB2 + (size_t)b * DENZ + d] = a2;
    g_scratch[OFF_XB4 + (size_t)b * DENZ + d] = a4;
}

// ==================== final GEMVs ====================
__global__ __launch_bounds__(512) void final_out(
        const float* __restrict__ Wv0, const float* __restrict__ bv0,
        const float* __restrict__ Wv1, const float* __restrict__ bv1,
        const float* __restrict__ Wv2, const float* __restrict__ bv2,
        const float* __restrict__ Wv3, const float* __restrict__ bv3,
        float* __restrict__ out) {
    int b = blockIdx.x, p = blockIdx.y, d = threadIdx.x;
    const float* xb; const float* Wv; const float* bv; int Kd;
    if (p == 0)      { xb = g_scratch + OFF_XB1 + (size_t)b * DCPD; Wv = Wv0; bv = bv0; Kd = DCPD; }
    else if (p == 1) { xb = g_scratch + OFF_XB2 + (size_t)b * DENZ; Wv = Wv1; bv = bv1; Kd = DENZ; }
    else if (p == 2) { xb = g_scratch + OFF_XB3 + (size_t)b * DCPD; Wv = Wv2; bv = bv2; Kd = DCPD; }
    else             { xb = g_scratch + OFF_XB4 + (size_t)b * DENZ; Wv = Wv3; bv = bv3; Kd = DENZ; }

    __shared__ float xs[DENZ];
    for (int i = threadIdx.x; i < Kd; i += 512) xs[i] = xb[i];
    __syncthreads();

    float acc = bv[d];
#pragma unroll 4
    for (int j = 0; j < Kd; j++) acc += xs[j] * Wv[(size_t)j * DOUT + d];
    out[(size_t)b * 2048 + p * 512 + d] = acc;
}

// ==================== launch ====================
extern "C" void kernel_launch(void* const* d_in, const int* in_sizes, int n_in,
                              void* d_out, int out_size) {
    const float* enz   = (const float*)d_in[0];
    const float* subs  = (const float*)d_in[1];
    const float* prod  = (const float*)d_in[2];
    const float* IW    = (const float*)d_in[6];
    const float* enz_Wq = (const float*)d_in[7];
    const float* enz_bq = (const float*)d_in[8];
    const float* enz_Wk = (const float*)d_in[9];
    const float* enz_bk = (const float*)d_in[10];
    const float* enz_Wv = (const float*)d_in[11];
    const float* enz_bv = (const float*)d_in[12];
    const float* sub_Wq = (const float*)d_in[13];
    const float* sub_bq = (const float*)d_in[14];
    const float* sub_Wk = (const float*)d_in[15];
    const float* sub_bk = (const float*)d_in[16];
    const float* sub_Wv = (const float*)d_in[17];
    const float* sub_bv = (const float*)d_in[18];
    const float* prod_Wq = (const float*)d_in[19];
    const float* prod_bq = (const float*)d_in[20];
    const float* prod_Wk = (const float*)d_in[21];
    const float* prod_bk = (const float*)d_in[22];
    const float* prod_Wv = (const float*)d_in[23];
    const float* prod_bv = (const float*)d_in[24];
    float* out = (float*)d_out;

    static float* gs = nullptr;
    static __nv_bfloat16 *Ah = nullptr, *Al = nullptr, *Wht = nullptr, *Wlt = nullptr;
    static __nv_bfloat16 *X2h = nullptr, *X2l = nullptr, *W2h = nullptr, *W2l = nullptr;
    static __nv_bfloat16 *QKh = nullptr, *QKl = nullptr, *Ch = nullptr, *Cl = nullptr;
    static bool inited = false;
    if (!inited) {
        void* p = nullptr;
        cudaGetSymbolAddress(&p, g_scratch);  gs = (float*)p;
        cudaGetSymbolAddress(&p, g_Ah);       Ah = (__nv_bfloat16*)p;
        cudaGetSymbolAddress(&p, g_Al);       Al = (__nv_bfloat16*)p;
        cudaGetSymbolAddress(&p, g_Wht);      Wht = (__nv_bfloat16*)p;
        cudaGetSymbolAddress(&p, g_Wlt);      Wlt = (__nv_bfloat16*)p;
        cudaGetSymbolAddress(&p, g_X2h);      X2h = (__nv_bfloat16*)p;
        cudaGetSymbolAddress(&p, g_X2l);      X2l = (__nv_bfloat16*)p;
        cudaGetSymbolAddress(&p, g_W2h);      W2h = (__nv_bfloat16*)p;
        cudaGetSymbolAddress(&p, g_W2l);      W2l = (__nv_bfloat16*)p;
        cudaGetSymbolAddress(&p, g_QKh);      QKh = (__nv_bfloat16*)p;
        cudaGetSymbolAddress(&p, g_QKl);      QKl = (__nv_bfloat16*)p;
        cudaGetSymbolAddress(&p, g_Ch);       Ch = (__nv_bfloat16*)p;
        cudaGetSymbolAddress(&p, g_Cl);       Cl = (__nv_bfloat16*)p;
        cudaFuncSetAttribute(hmma_nn_kernel,
                             cudaFuncAttributeMaxDynamicSharedMemorySize, SMEM_MMA_BYTES);
        cudaFuncSetAttribute(score_kernel,
                             cudaFuncAttributeMaxDynamicSharedMemorySize, SMEM_MMA_BYTES);
        inited = true;
    }

    // #1: merged head (all conversions + biases + zeroing)
    head_kernel<<<HB9, 256>>>(enz, subs, prod,
                              enz_Wq, enz_bq, enz_Wk, enz_bk,
                              sub_Wq, sub_bq, sub_Wk, sub_bk,
                              prod_Wq, prod_bq, prod_Wk, prod_bk);

    // #2, #3: cpd projections on HMMA
    hmma_nn_kernel<<<dim3(1024 / 128, (NB * LCPD) / 128), 256, SMEM_MMA_BYTES>>>(
        X2h, X2l, W2h, W2l, gs + OFF_BCS, Ch, Cl, DCPD, 1024);
    hmma_nn_kernel<<<dim3(1024 / 128, (NB * LCPD) / 128), 256, SMEM_MMA_BYTES>>>(
        X2h + N_CPD, X2l + N_CPD, W2h + N_W2, W2l + N_W2,
        gs + OFF_BCP, Ch + CPOFF, Cl + CPOFF, DCPD, 1024);

    // #4: BIG projection (positioned 4th for ncu capture)
    hmma_nn_kernel<<<dim3(1536 / 128, (NB * LENZ) / 128), 256, SMEM_MMA_BYTES>>>(
        Ah, Al, Wht, Wlt, gs + OFF_BCE, QKh, QKl, DENZ, 1536);

    // #5: all four score GEMMs
    score_kernel<<<dim3(4, 1, 128), 256, SMEM_MMA_BYTES>>>(IW);

    // #6: all four softmax+mean reductions
    softmax_all<<<dim3(NB, 8, 4), 256>>>();

    // #7, #8: weighted feature sums
    wfeat_small2<<<dim3(NB, 4, 2), 256>>>(subs, prod);
    wfeat_enz<<<dim3(NB, DENZ / 256), 256>>>(enz);

    // #9: final GEMVs
    final_out<<<dim3(NB, 4), 512>>>(enz_Wv, enz_bv,
                                    sub_Wv, sub_bv,
                                    enz_Wv, enz_bv,
                                    prod_Wv, prod_bv,
                                    out);
}